// round 4
// baseline (speedup 1.0000x reference)
#include <cuda_runtime.h>
#include <cuda_bf16.h>
#include <cstdint>

// ---------------- problem constants ----------------
#define BATCHES   16
#define NC_PER    1024
#define NF_PER    4096
#define NC_TOT    (BATCHES * NC_PER)   // 16384
#define NF_TOT    (BATCHES * NF_PER)   // 65536
#define C_IN      512
#define C_SKIP    256
#define D_IN      (C_IN + C_SKIP)      // 768
#define C_OUT     512
#define BN_EPS    1e-5f
#define NMBLK     (NF_TOT / 128)       // 512 m-blocks

// ---------------- device scratch ----------------
__device__ __align__(128) __nv_bfloat16 g_h0hi[(size_t)NF_TOT * D_IN];
__device__ __align__(128) __nv_bfloat16 g_h0lo[(size_t)NF_TOT * D_IN];
__device__ __align__(128) uint32_t      g_h1p[(size_t)NF_TOT * C_OUT];  // packed bf16 hi|lo
__device__ __align__(128) uint32_t      g_h2p[(size_t)NF_TOT * C_OUT];
__device__ __align__(128) __nv_bfloat16 g_w1thi[(size_t)C_OUT * D_IN];
__device__ __align__(128) __nv_bfloat16 g_w1tlo[(size_t)C_OUT * D_IN];
__device__ __align__(128) __nv_bfloat16 g_w2thi[(size_t)C_OUT * C_OUT];
__device__ __align__(128) __nv_bfloat16 g_w2tlo[(size_t)C_OUT * C_OUT];
__device__ int   g_kidx[(size_t)NF_TOT * 3];
__device__ float g_kw[(size_t)NF_TOT * 3];
__device__ float g_psum[NMBLK * C_OUT];
__device__ float g_psq[NMBLK * C_OUT];
__device__ float g_a1[C_OUT], g_c1[C_OUT], g_a2[C_OUT], g_c2[C_OUT];

// ---------------- helpers ----------------
__device__ __forceinline__ uint32_t smem_u32(const void* p) {
    uint32_t a;
    asm("{ .reg .u64 t; cvta.to.shared.u64 t, %1; cvt.u32.u64 %0, t; }" : "=r"(a) : "l"(p));
    return a;
}
__device__ __forceinline__ void cp16(uint32_t dst, const void* src) {
    asm volatile("cp.async.cg.shared.global [%0], [%1], 16;" :: "r"(dst), "l"(src));
}
__device__ __forceinline__ void cp_commit() {
    asm volatile("cp.async.commit_group;" ::: "memory");
}
__device__ __forceinline__ void cp_wait1() {
    asm volatile("cp.async.wait_group 1;" ::: "memory");
}
__device__ __forceinline__ void ldsm4(uint32_t& r0, uint32_t& r1, uint32_t& r2, uint32_t& r3, uint32_t addr) {
    asm volatile("ldmatrix.sync.aligned.m8n8.x4.shared.b16 {%0,%1,%2,%3}, [%4];"
                 : "=r"(r0), "=r"(r1), "=r"(r2), "=r"(r3) : "r"(addr));
}
__device__ __forceinline__ void mma16816(float* c, const uint32_t* a, const uint32_t* b) {
    asm volatile("mma.sync.aligned.m16n8k16.row.col.f32.bf16.bf16.f32 "
                 "{%0,%1,%2,%3}, {%4,%5,%6,%7}, {%8,%9}, {%0,%1,%2,%3};"
                 : "+f"(c[0]), "+f"(c[1]), "+f"(c[2]), "+f"(c[3])
                 : "r"(a[0]), "r"(a[1]), "r"(a[2]), "r"(a[3]), "r"(b[0]), "r"(b[1]));
}
__device__ __forceinline__ void split2(float v, __nv_bfloat16& h, __nv_bfloat16& l) {
    h = __float2bfloat16(v);
    l = __float2bfloat16(v - __bfloat162float(h));
}
// pack value as (hi_bf16 << 16) | lo_bf16
__device__ __forceinline__ uint32_t pack_bf2(float y) {
    __nv_bfloat16 hb, lb;
    split2(y, hb, lb);
    return ((uint32_t)__bfloat16_as_ushort(hb) << 16) | (uint32_t)__bfloat16_as_ushort(lb);
}
__device__ __forceinline__ float unpack_bf2(uint32_t w) {
    float hi = __uint_as_float(w & 0xFFFF0000u);
    float lo = __uint_as_float(w << 16);
    return hi + lo;
}

// ---------------- kNN (K=3) ----------------
__global__ __launch_bounds__(256) void knn_kernel(
    const float* __restrict__ pos, const float* __restrict__ pos_skip,
    int* __restrict__ idx_out, float* __restrict__ w_out)
{
    __shared__ float sx[NC_PER], sy[NC_PER], sz[NC_PER], sn[NC_PER];
    int blk = blockIdx.x;
    int b = blk >> 4;
    const float* pc = pos + (size_t)b * NC_PER * 3;
    for (int i = threadIdx.x; i < NC_PER; i += 256) {
        float px = pc[i*3+0], py = pc[i*3+1], pz = pc[i*3+2];
        sx[i] = px; sy[i] = py; sz[i] = pz;
        sn[i] = px*px + py*py + pz*pz;
    }
    __syncthreads();
    int f = blk * 256 + threadIdx.x;
    float fx = pos_skip[f*3+0], fy = pos_skip[f*3+1], fz = pos_skip[f*3+2];
    float fn = fx*fx + fy*fy + fz*fz;
    float d0 = 3.4e38f, d1 = 3.4e38f, d2 = 3.4e38f;
    int   i0 = 0, i1 = 0, i2 = 0;
    for (int c = 0; c < NC_PER; ++c) {
        float dot = fx*sx[c] + fy*sy[c] + fz*sz[c];
        float dd  = fn + sn[c] - 2.0f*dot;
        if (dd < d2) {
            if (dd < d1) {
                if (dd < d0) { d2=d1; i2=i1; d1=d0; i1=i0; d0=dd; i0=c; }
                else         { d2=d1; i2=i1; d1=dd; i1=c; }
            } else           { d2=dd; i2=c; }
        }
    }
    float w0 = 1.0f / fmaxf(d0, 1e-16f);
    float w1 = 1.0f / fmaxf(d1, 1e-16f);
    float w2 = 1.0f / fmaxf(d2, 1e-16f);
    float inv = 1.0f / (w0 + w1 + w2);
    idx_out[f*3+0] = b * NC_PER + i0;
    idx_out[f*3+1] = b * NC_PER + i1;
    idx_out[f*3+2] = b * NC_PER + i2;
    w_out[f*3+0] = w0 * inv;
    w_out[f*3+1] = w1 * inv;
    w_out[f*3+2] = w2 * inv;
}

// ---------------- interpolate + concat -> bf16 hi/lo h0 ----------------
__global__ __launch_bounds__(128) void interp_kernel(
    const float* __restrict__ x, const float* __restrict__ x_skip)
{
    int f = blockIdx.x;
    int t = threadIdx.x;
    int ia = g_kidx[f*3+0], ib = g_kidx[f*3+1], ic = g_kidx[f*3+2];
    float w0 = g_kw[f*3+0], w1 = g_kw[f*3+1], w2 = g_kw[f*3+2];
    float4 a = ((const float4*)(x + (size_t)ia * C_IN))[t];
    float4 b = ((const float4*)(x + (size_t)ib * C_IN))[t];
    float4 c = ((const float4*)(x + (size_t)ic * C_IN))[t];
    float r[4];
    r[0] = w0*a.x + w1*b.x + w2*c.x;
    r[1] = w0*a.y + w1*b.y + w2*c.y;
    r[2] = w0*a.z + w1*b.z + w2*c.z;
    r[3] = w0*a.w + w1*b.w + w2*c.w;
    __nv_bfloat16 h[4], l[4];
    #pragma unroll
    for (int j = 0; j < 4; ++j) split2(r[j], h[j], l[j]);
    size_t base = (size_t)f * D_IN + t * 4;
    *(uint2*)(g_h0hi + base) = *(uint2*)h;
    *(uint2*)(g_h0lo + base) = *(uint2*)l;
    if (t < C_SKIP / 4) {
        float4 s = ((const float4*)(x_skip + (size_t)f * C_SKIP))[t];
        float sv[4] = {s.x, s.y, s.z, s.w};
        #pragma unroll
        for (int j = 0; j < 4; ++j) split2(sv[j], h[j], l[j]);
        size_t base2 = (size_t)f * D_IN + C_IN + t * 4;
        *(uint2*)(g_h0hi + base2) = *(uint2*)h;
        *(uint2*)(g_h0lo + base2) = *(uint2*)l;
    }
}

// ---------------- W transpose + split: Wt[n][k] = W[k][n] ----------------
__global__ __launch_bounds__(256) void wsplit_kernel(
    const float* __restrict__ W, __nv_bfloat16* __restrict__ hi,
    __nv_bfloat16* __restrict__ lo, int Kd, int N)
{
    int id = blockIdx.x * 256 + threadIdx.x;
    if (id >= N * Kd) return;
    int n = id / Kd, k = id % Kd;
    float v = W[(size_t)k * N + n];
    __nv_bfloat16 h, l;
    split2(v, h, l);
    hi[id] = h; lo[id] = l;
}

// ---------------- HMMA split-2 bf16 GEMM with fused BN stats + packed output ----------------
// MODE 0 (GEMM1): A via cp.async from Ahi/Alo buffers (raw h0).
// MODE 1 (GEMM2): A from packed h1p via LDG -> BN1 affine+ReLU -> split -> STS.
// Epilogue: packed bf16 hi/lo output + deterministic per-m-block column sum/sumsq.
#define BK 64
#define REG_BYTES 16384                  // one 128x64 bf16 tile
#define STAGE_BYTES (4 * REG_BYTES)      // Ahi | Alo | Bhi | Blo
#define STAGES 3
#define SM_STAGE_TOT (STAGES * STAGE_BYTES)        // 196608
#define SM_AL   (SM_STAGE_TOT)                     // salpha 2048
#define SM_CN   (SM_AL + 2048)                     // scnst  2048
#define SM_RS   (SM_CN + 2048)                     // sred sum 4*128*4 = 2048
#define SM_RQ   (SM_RS + 2048)                     // sred sq 2048
#define GEMM_SMEM (SM_RQ + 2048)                   // 204800

__device__ __forceinline__ uint32_t swoff(int row, int c) {
    return (uint32_t)(row * 128 + ((c ^ (row & 7)) << 4));
}

template<int MODE>
__global__ __launch_bounds__(256, 1) void gemm_kernel(
    const __nv_bfloat16* __restrict__ Ahi, const __nv_bfloat16* __restrict__ Alo,
    const uint32_t* __restrict__ Apk,
    const __nv_bfloat16* __restrict__ Bhi, const __nv_bfloat16* __restrict__ Blo,
    const float* __restrict__ alpha, const float* __restrict__ cnst,
    uint32_t* __restrict__ Cpk, float* __restrict__ psum, float* __restrict__ psq,
    int Kd, int nchunk)
{
    extern __shared__ __align__(128) char smem[];
    uint32_t sbase = smem_u32(smem);
    int tid  = threadIdx.x;
    int wid  = tid >> 5, lane = tid & 31;
    int m0 = blockIdx.y * 128;
    int n0 = blockIdx.x * 128;

    float* salpha = (float*)(smem + SM_AL);
    float* scnst  = (float*)(smem + SM_CN);
    if (MODE == 1) {
        if (tid < 128) {
            salpha[tid] = alpha[tid]; salpha[tid+128] = alpha[tid+128];
            salpha[tid+256] = alpha[tid+256]; salpha[tid+384] = alpha[tid+384];
            scnst[tid] = cnst[tid]; scnst[tid+128] = cnst[tid+128];
            scnst[tid+256] = cnst[tid+256]; scnst[tid+384] = cnst[tid+384];
        }
        __syncthreads();
    }

    const __nv_bfloat16* bsrc[2] = { Bhi + (size_t)n0 * Kd, Blo + (size_t)n0 * Kd };
    const __nv_bfloat16* asrc[2] = { (MODE == 0) ? Ahi + (size_t)m0 * Kd : nullptr,
                                     (MODE == 0) ? Alo + (size_t)m0 * Kd : nullptr };

    // ---- cp.async issue: B (and A in MODE 0) ----
    auto issueB = [&](int sidx, int k0) {
        uint32_t sb = sbase + (uint32_t)sidx * STAGE_BYTES;
        if (MODE == 0) {
            #pragma unroll
            for (int reg = 0; reg < 2; ++reg) {
                uint32_t rb = sb + (uint32_t)reg * REG_BYTES;
                #pragma unroll
                for (int it = 0; it < 4; ++it) {
                    int chunk = it * 256 + tid;
                    int row = chunk >> 3, c = chunk & 7;
                    cp16(rb + swoff(row, c), asrc[reg] + (size_t)row * Kd + k0 + c * 8);
                }
            }
        }
        #pragma unroll
        for (int reg = 0; reg < 2; ++reg) {
            uint32_t rb = sb + (uint32_t)(2 + reg) * REG_BYTES;
            #pragma unroll
            for (int it = 0; it < 4; ++it) {
                int chunk = it * 256 + tid;
                int row = chunk >> 3, c = chunk & 7;
                cp16(rb + swoff(row, c), bsrc[reg] + (size_t)row * Kd + k0 + c * 8);
            }
        }
    };

    // ---- MODE 1 A path: LDG packed -> regs ----
    uint4 rA[4][2];
    auto ldgA = [&](int k0) {
        if (MODE != 1) return;
        #pragma unroll
        for (int it = 0; it < 4; ++it) {
            int chunk = it * 256 + tid;
            int row = chunk >> 3, c = chunk & 7;
            const uint4* src = (const uint4*)(Apk + (size_t)(m0 + row) * C_OUT + k0 + c * 8);
            rA[it][0] = __ldg(src);
            rA[it][1] = __ldg(src + 1);
        }
    };
    // transform (affine+relu+split) and store to stage
    auto stA = [&](int sidx, int k0) {
        if (MODE != 1) return;
        uint32_t sb = sbase + (uint32_t)sidx * STAGE_BYTES;
        #pragma unroll
        for (int it = 0; it < 4; ++it) {
            int chunk = it * 256 + tid;
            int row = chunk >> 3, c = chunk & 7;
            int kb = k0 + c * 8;
            float av[8], cv[8];
            *(float4*)(av)     = *(float4*)(salpha + kb);
            *(float4*)(av + 4) = *(float4*)(salpha + kb + 4);
            *(float4*)(cv)     = *(float4*)(scnst + kb);
            *(float4*)(cv + 4) = *(float4*)(scnst + kb + 4);
            uint32_t w[8];
            *(uint4*)(w)     = rA[it][0];
            *(uint4*)(w + 4) = rA[it][1];
            uint32_t hiw[4], low[4];
            #pragma unroll
            for (int j2 = 0; j2 < 4; ++j2) {
                uint32_t p0, p1;
                #pragma unroll
                for (int s = 0; s < 2; ++s) {
                    int j = j2 * 2 + s;
                    float v = unpack_bf2(w[j]);
                    float y = fmaxf(fmaf(av[j], v, cv[j]), 0.0f);
                    __nv_bfloat16 hb, lb;
                    split2(y, hb, lb);
                    uint32_t hu = __bfloat16_as_ushort(hb);
                    uint32_t lu = __bfloat16_as_ushort(lb);
                    if (s == 0) { p0 = hu; p1 = lu; }
                    else { p0 |= hu << 16; p1 |= lu << 16; }
                }
                hiw[j2] = p0; low[j2] = p1;
            }
            uint32_t off = swoff(row, c);
            asm volatile("st.shared.v4.b32 [%0], {%1,%2,%3,%4};"
                         :: "r"(sb + off), "r"(hiw[0]), "r"(hiw[1]), "r"(hiw[2]), "r"(hiw[3]));
            asm volatile("st.shared.v4.b32 [%0], {%1,%2,%3,%4};"
                         :: "r"(sb + REG_BYTES + off), "r"(low[0]), "r"(low[1]), "r"(low[2]), "r"(low[3]));
        }
    };

    // ---- prologue ----
    if (MODE == 1) { ldgA(0); }
    issueB(0, 0);  cp_commit();
    if (MODE == 1) { stA(0, 0); ldgA(BK); }
    issueB(1, BK); cp_commit();
    if (MODE == 1) { stA(1, BK); }

    // warp tiling: 4 (M) x 2 (N) warps; warp tile 32(M) x 64(N)
    int wm = wid & 3, wn = wid >> 2;
    int mbase = wm * 32, nbase = wn * 64;
    int sub = lane >> 3, l7 = lane & 7;

    float acc[2][8][4];
    #pragma unroll
    for (int i = 0; i < 2; ++i)
        #pragma unroll
        for (int j = 0; j < 8; ++j)
            #pragma unroll
            for (int q = 0; q < 4; ++q) acc[i][j][q] = 0.0f;

    int arow_l = mbase + ((sub & 1) << 3) + l7;
    int acol_s = (sub >> 1);
    int brow_l = nbase + ((sub >> 1) << 3) + l7;
    int bcol_s = (sub & 1);

    for (int cc = 0; cc < nchunk; ++cc) {
        cp_wait1();
        __syncthreads();
        bool pre = (cc + 2 < nchunk);
        if (pre) {
            if (MODE == 1) ldgA((cc + 2) * BK);
            issueB((cc + 2) % STAGES, (cc + 2) * BK);
        }
        cp_commit();

        uint32_t bb = sbase + (uint32_t)(cc % STAGES) * STAGE_BYTES;
        #pragma unroll
        for (int ks = 0; ks < 4; ++ks) {
            uint32_t ah[2][4], al[2][4], bh[8][2], bl[8][2];
            int achunk = ks * 2 + acol_s;
            #pragma unroll
            for (int mi = 0; mi < 2; ++mi) {
                uint32_t ao = swoff(arow_l + mi * 16, achunk);
                ldsm4(ah[mi][0], ah[mi][1], ah[mi][2], ah[mi][3], bb + ao);
                ldsm4(al[mi][0], al[mi][1], al[mi][2], al[mi][3], bb + REG_BYTES + ao);
            }
            int bchunk = ks * 2 + bcol_s;
            #pragma unroll
            for (int pi = 0; pi < 4; ++pi) {
                uint32_t bo = swoff(brow_l + pi * 16, bchunk);
                ldsm4(bh[pi*2][0], bh[pi*2][1], bh[pi*2+1][0], bh[pi*2+1][1],
                      bb + 2 * REG_BYTES + bo);
                ldsm4(bl[pi*2][0], bl[pi*2][1], bl[pi*2+1][0], bl[pi*2+1][1],
                      bb + 3 * REG_BYTES + bo);
            }
            #pragma unroll
            for (int mi = 0; mi < 2; ++mi)
                #pragma unroll
                for (int ni = 0; ni < 8; ++ni)
                    mma16816(acc[mi][ni], ah[mi], bh[ni]);
            #pragma unroll
            for (int mi = 0; mi < 2; ++mi)
                #pragma unroll
                for (int ni = 0; ni < 8; ++ni)
                    mma16816(acc[mi][ni], ah[mi], bl[ni]);
            #pragma unroll
            for (int mi = 0; mi < 2; ++mi)
                #pragma unroll
                for (int ni = 0; ni < 8; ++ni)
                    mma16816(acc[mi][ni], al[mi], bh[ni]);
        }
        if (pre && MODE == 1) stA((cc + 2) % STAGES, (cc + 2) * BK);
    }

    // ---- epilogue: packed store + fused column stats ----
    int grow = m0 + mbase + (lane >> 2);
    int gcol0 = n0 + nbase + (lane & 3) * 2;
    #pragma unroll
    for (int ni = 0; ni < 8; ++ni) {
        int col = gcol0 + ni * 8;
        #pragma unroll
        for (int mi = 0; mi < 2; ++mi) {
            int r = grow + mi * 16;
            uint2 w0 = make_uint2(pack_bf2(acc[mi][ni][0]), pack_bf2(acc[mi][ni][1]));
            uint2 w1 = make_uint2(pack_bf2(acc[mi][ni][2]), pack_bf2(acc[mi][ni][3]));
            *(uint2*)(Cpk + (size_t)r * C_OUT + col)       = w0;
            *(uint2*)(Cpk + (size_t)(r + 8) * C_OUT + col) = w1;
        }
    }
    // per-thread column partials (16 columns per thread), exact fp32 accumulators
    float scol[16], qcol[16];
    #pragma unroll
    for (int ni = 0; ni < 8; ++ni) {
        #pragma unroll
        for (int ch = 0; ch < 2; ++ch) {
            float v0 = acc[0][ni][ch],     v1 = acc[0][ni][ch + 2];
            float v2 = acc[1][ni][ch],     v3 = acc[1][ni][ch + 2];
            scol[ni*2+ch] = (v0 + v1) + (v2 + v3);
            qcol[ni*2+ch] = (v0*v0 + v1*v1) + (v2*v2 + v3*v3);
        }
    }
    #pragma unroll
    for (int t = 0; t < 16; ++t) {
        #pragma unroll
        for (int m = 4; m <= 16; m <<= 1) {
            scol[t] += __shfl_xor_sync(0xFFFFFFFFu, scol[t], m);
            qcol[t] += __shfl_xor_sync(0xFFFFFFFFu, qcol[t], m);
        }
    }
    float* sred_s = (float*)(smem + SM_RS);
    float* sred_q = (float*)(smem + SM_RQ);
    if (lane < 4) {
        #pragma unroll
        for (int ni = 0; ni < 8; ++ni) {
            #pragma unroll
            for (int ch = 0; ch < 2; ++ch) {
                int cidx = wn * 64 + lane * 2 + ni * 8 + ch;
                sred_s[wm * 128 + cidx] = scol[ni*2+ch];
                sred_q[wm * 128 + cidx] = qcol[ni*2+ch];
            }
        }
    }
    __syncthreads();
    if (tid < 128) {
        float s = ((sred_s[tid] + sred_s[128 + tid]) + (sred_s[256 + tid] + sred_s[384 + tid]));
        float q = ((sred_q[tid] + sred_q[128 + tid]) + (sred_q[256 + tid] + sred_q[384 + tid]));
        psum[(size_t)blockIdx.y * C_OUT + n0 + tid] = s;
        psq [(size_t)blockIdx.y * C_OUT + n0 + tid] = q;
    }
}

// ---------------- finalize: fold 512 m-block partials -> affine coefs ----------------
__global__ __launch_bounds__(128) void finalize_kernel(
    const float* __restrict__ g, const float* __restrict__ be,
    float* __restrict__ a, float* __restrict__ c)
{
    int ch = blockIdx.x * 128 + threadIdx.x;
    float s = 0, q = 0;
    for (int p = 0; p < NMBLK; ++p) {
        s += g_psum[p * C_OUT + ch];
        q += g_psq [p * C_OUT + ch];
    }
    float mu  = s * (1.0f / NF_TOT);
    float var = q * (1.0f / NF_TOT) - mu * mu;
    float av  = g[ch] * rsqrtf(var + BN_EPS);
    a[ch] = av;
    c[ch] = be[ch] - mu * av;
}

// ---------------- final BN2 + ReLU from packed h2 -> out ----------------
__global__ __launch_bounds__(256) void apply_out_kernel(
    const uint32_t* __restrict__ Hp, float* __restrict__ out)
{
    size_t i = (size_t)blockIdx.x * 256 + threadIdx.x;   // one uint4 = 4 channels
    int cb = (int)(i & (C_OUT/4 - 1));
    uint4 w = ((const uint4*)Hp)[i];
    float4 av = ((const float4*)g_a2)[cb];
    float4 cv = ((const float4*)g_c2)[cb];
    float4 r;
    r.x = fmaxf(fmaf(av.x, unpack_bf2(w.x), cv.x), 0.0f);
    r.y = fmaxf(fmaf(av.y, unpack_bf2(w.y), cv.y), 0.0f);
    r.z = fmaxf(fmaf(av.z, unpack_bf2(w.z), cv.z), 0.0f);
    r.w = fmaxf(fmaf(av.w, unpack_bf2(w.w), cv.w), 0.0f);
    ((float4*)out)[i] = r;
}

// ---------------- tuple extras ----------------
__global__ __launch_bounds__(256) void extras_kernel(
    const float* __restrict__ pos_skip, float* __restrict__ out, int mode)
{
    int i = blockIdx.x * 256 + threadIdx.x;
    const size_t baseH = (size_t)NF_TOT * C_OUT;
    if (i < NF_TOT * 3) out[baseH + i] = pos_skip[i];
    if (i < NF_TOT) {
        if (mode == 1)
            out[baseH + NF_TOT*3 + i] = (float)(i >> 12);
        else if (mode == 2)
            ((long long*)(out + baseH + NF_TOT*3))[i] = (long long)(i >> 12);
    }
}

// ---------------- host ----------------
extern "C" void kernel_launch(void* const* d_in, const int* in_sizes, int n_in,
                              void* d_out, int out_size)
{
    const float* x        = (const float*)d_in[0];
    const float* pos      = (const float*)d_in[1];
    const float* x_skip   = (const float*)d_in[3];
    const float* pos_skip = (const float*)d_in[4];
    const float* W1  = (const float*)d_in[6];
    const float* g1  = (const float*)d_in[8];
    const float* be1 = (const float*)d_in[9];
    const float* W2  = (const float*)d_in[10];
    const float* g2  = (const float*)d_in[12];
    const float* be2 = (const float*)d_in[13];
    float* out = (float*)d_out;

    float *p_a1, *p_c1, *p_a2, *p_c2, *p_psum, *p_psq;
    cudaGetSymbolAddress((void**)&p_a1, g_a1);
    cudaGetSymbolAddress((void**)&p_c1, g_c1);
    cudaGetSymbolAddress((void**)&p_a2, g_a2);
    cudaGetSymbolAddress((void**)&p_c2, g_c2);
    cudaGetSymbolAddress((void**)&p_psum, g_psum);
    cudaGetSymbolAddress((void**)&p_psq, g_psq);
    int *p_kidx; float *p_kw;
    cudaGetSymbolAddress((void**)&p_kidx, g_kidx);
    cudaGetSymbolAddress((void**)&p_kw,   g_kw);
    uint32_t *p_h1p, *p_h2p;
    cudaGetSymbolAddress((void**)&p_h1p, g_h1p);
    cudaGetSymbolAddress((void**)&p_h2p, g_h2p);
    __nv_bfloat16 *p_h0hi, *p_h0lo, *p_w1thi, *p_w1tlo, *p_w2thi, *p_w2tlo;
    cudaGetSymbolAddress((void**)&p_h0hi, g_h0hi);
    cudaGetSymbolAddress((void**)&p_h0lo, g_h0lo);
    cudaGetSymbolAddress((void**)&p_w1thi, g_w1thi);
    cudaGetSymbolAddress((void**)&p_w1tlo, g_w1tlo);
    cudaGetSymbolAddress((void**)&p_w2thi, g_w2thi);
    cudaGetSymbolAddress((void**)&p_w2tlo, g_w2tlo);

    cudaFuncSetAttribute(gemm_kernel<0>, cudaFuncAttributeMaxDynamicSharedMemorySize, GEMM_SMEM);
    cudaFuncSetAttribute(gemm_kernel<1>, cudaFuncAttributeMaxDynamicSharedMemorySize, GEMM_SMEM);

    // weight prep
    wsplit_kernel<<<(C_OUT * D_IN + 255) / 256, 256>>>(W1, p_w1thi, p_w1tlo, D_IN, C_OUT);
    wsplit_kernel<<<(C_OUT * C_OUT + 255) / 256, 256>>>(W2, p_w2thi, p_w2tlo, C_OUT, C_OUT);
    // 1) kNN
    knn_kernel<<<NF_TOT / 256, 256>>>(pos, pos_skip, p_kidx, p_kw);
    // 2) interpolate + concat -> h0 hi/lo
    interp_kernel<<<NF_TOT, 128>>>(x, x_skip);
    // 3) GEMM1 -> packed h1 + fused BN1 stats  (bias dropped: BN is shift-invariant)
    {
        dim3 grid(C_OUT / 128, NF_TOT / 128);
        gemm_kernel<0><<<grid, 256, GEMM_SMEM>>>(p_h0hi, p_h0lo, nullptr,
                                                 p_w1thi, p_w1tlo, nullptr, nullptr,
                                                 p_h1p, p_psum, p_psq, D_IN, D_IN / BK);
    }
    finalize_kernel<<<C_OUT / 128, 128>>>(g1, be1, p_a1, p_c1);
    // 4) GEMM2 (BN1 affine+ReLU fused in A-load) -> packed h2 + fused BN2 stats
    {
        dim3 grid(C_OUT / 128, NF_TOT / 128);
        gemm_kernel<1><<<grid, 256, GEMM_SMEM>>>(nullptr, nullptr, p_h1p,
                                                 p_w2thi, p_w2tlo, p_a1, p_c1,
                                                 p_h2p, p_psum, p_psq, C_OUT, C_OUT / BK);
    }
    finalize_kernel<<<C_OUT / 128, 128>>>(g2, be2, p_a2, p_c2);
    // 5) BN2 + ReLU -> out
    apply_out_kernel<<<(NF_TOT * (C_OUT / 4)) / 256, 256>>>(p_h2p, out);
    // 6) tuple extras
    {
        long long baseH = (long long)NF_TOT * C_OUT;
        long long rem = (long long)out_size - baseH - (long long)NF_TOT * 3;
        int mode = 0;
        if (rem >= 2LL * NF_TOT)      mode = 2;
        else if (rem >= (long long)NF_TOT) mode = 1;
        if ((long long)out_size >= baseH + (long long)NF_TOT * 3)
            extras_kernel<<<(NF_TOT * 3 + 255) / 256, 256>>>(pos_skip, out, mode);
    }
}

// round 5
// speedup vs baseline: 1.1269x; 1.1269x over previous
#include <cuda_runtime.h>
#include <cuda_bf16.h>
#include <cstdint>

// ---------------- problem constants ----------------
#define BATCHES   16
#define NC_PER    1024
#define NF_PER    4096
#define NC_TOT    (BATCHES * NC_PER)   // 16384
#define NF_TOT    (BATCHES * NF_PER)   // 65536
#define C_IN      512
#define C_SKIP    256
#define D_IN      (C_IN + C_SKIP)      // 768
#define C_OUT     512
#define BN_EPS    1e-5f
#define NMBLK     (NF_TOT / 128)       // 512 m-blocks

// ---------------- device scratch ----------------
__device__ __align__(128) __nv_bfloat16 g_h0hi[(size_t)NF_TOT * D_IN];
__device__ __align__(128) __nv_bfloat16 g_h0lo[(size_t)NF_TOT * D_IN];
__device__ __align__(128) float         g_h1[(size_t)NF_TOT * C_OUT];
__device__ __align__(128) float         g_h2[(size_t)NF_TOT * C_OUT];
__device__ __align__(128) __nv_bfloat16 g_h1hi[(size_t)NF_TOT * C_OUT];
__device__ __align__(128) __nv_bfloat16 g_h1lo[(size_t)NF_TOT * C_OUT];
__device__ __align__(128) __nv_bfloat16 g_w1thi[(size_t)C_OUT * D_IN];
__device__ __align__(128) __nv_bfloat16 g_w1tlo[(size_t)C_OUT * D_IN];
__device__ __align__(128) __nv_bfloat16 g_w2thi[(size_t)C_OUT * C_OUT];
__device__ __align__(128) __nv_bfloat16 g_w2tlo[(size_t)C_OUT * C_OUT];
__device__ int   g_kidx[(size_t)NF_TOT * 3];
__device__ float g_kw[(size_t)NF_TOT * 3];
__device__ float g_psum[NMBLK * C_OUT];
__device__ float g_psq[NMBLK * C_OUT];
__device__ float g_a1[C_OUT], g_c1[C_OUT], g_a2[C_OUT], g_c2[C_OUT];

// ---------------- helpers ----------------
__device__ __forceinline__ uint32_t smem_u32(const void* p) {
    uint32_t a;
    asm("{ .reg .u64 t; cvta.to.shared.u64 t, %1; cvt.u32.u64 %0, t; }" : "=r"(a) : "l"(p));
    return a;
}
__device__ __forceinline__ void cp16(uint32_t dst, const void* src) {
    asm volatile("cp.async.cg.shared.global [%0], [%1], 16;" :: "r"(dst), "l"(src));
}
__device__ __forceinline__ void cp_commit() {
    asm volatile("cp.async.commit_group;" ::: "memory");
}
__device__ __forceinline__ void cp_wait1() {
    asm volatile("cp.async.wait_group 1;" ::: "memory");
}
__device__ __forceinline__ void ldsm4(uint32_t& r0, uint32_t& r1, uint32_t& r2, uint32_t& r3, uint32_t addr) {
    asm volatile("ldmatrix.sync.aligned.m8n8.x4.shared.b16 {%0,%1,%2,%3}, [%4];"
                 : "=r"(r0), "=r"(r1), "=r"(r2), "=r"(r3) : "r"(addr));
}
__device__ __forceinline__ void mma16816(float* c, const uint32_t* a, const uint32_t* b) {
    asm volatile("mma.sync.aligned.m16n8k16.row.col.f32.bf16.bf16.f32 "
                 "{%0,%1,%2,%3}, {%4,%5,%6,%7}, {%8,%9}, {%0,%1,%2,%3};"
                 : "+f"(c[0]), "+f"(c[1]), "+f"(c[2]), "+f"(c[3])
                 : "r"(a[0]), "r"(a[1]), "r"(a[2]), "r"(a[3]), "r"(b[0]), "r"(b[1]));
}
__device__ __forceinline__ void split2(float v, __nv_bfloat16& h, __nv_bfloat16& l) {
    h = __float2bfloat16(v);
    l = __float2bfloat16(v - __bfloat162float(h));
}

// ---------------- kNN (K=3) ----------------
__global__ __launch_bounds__(256) void knn_kernel(
    const float* __restrict__ pos, const float* __restrict__ pos_skip,
    int* __restrict__ idx_out, float* __restrict__ w_out)
{
    __shared__ float sx[NC_PER], sy[NC_PER], sz[NC_PER], sn[NC_PER];
    int blk = blockIdx.x;
    int b = blk >> 4;
    const float* pc = pos + (size_t)b * NC_PER * 3;
    for (int i = threadIdx.x; i < NC_PER; i += 256) {
        float px = pc[i*3+0], py = pc[i*3+1], pz = pc[i*3+2];
        sx[i] = px; sy[i] = py; sz[i] = pz;
        sn[i] = px*px + py*py + pz*pz;
    }
    __syncthreads();
    int f = blk * 256 + threadIdx.x;
    float fx = pos_skip[f*3+0], fy = pos_skip[f*3+1], fz = pos_skip[f*3+2];
    float fn = fx*fx + fy*fy + fz*fz;
    float d0 = 3.4e38f, d1 = 3.4e38f, d2 = 3.4e38f;
    int   i0 = 0, i1 = 0, i2 = 0;
    for (int c = 0; c < NC_PER; ++c) {
        float dot = fx*sx[c] + fy*sy[c] + fz*sz[c];
        float dd  = fn + sn[c] - 2.0f*dot;
        if (dd < d2) {
            if (dd < d1) {
                if (dd < d0) { d2=d1; i2=i1; d1=d0; i1=i0; d0=dd; i0=c; }
                else         { d2=d1; i2=i1; d1=dd; i1=c; }
            } else           { d2=dd; i2=c; }
        }
    }
    float w0 = 1.0f / fmaxf(d0, 1e-16f);
    float w1 = 1.0f / fmaxf(d1, 1e-16f);
    float w2 = 1.0f / fmaxf(d2, 1e-16f);
    float inv = 1.0f / (w0 + w1 + w2);
    idx_out[f*3+0] = b * NC_PER + i0;
    idx_out[f*3+1] = b * NC_PER + i1;
    idx_out[f*3+2] = b * NC_PER + i2;
    w_out[f*3+0] = w0 * inv;
    w_out[f*3+1] = w1 * inv;
    w_out[f*3+2] = w2 * inv;
}

// ---------------- interpolate + concat -> bf16 hi/lo h0 ----------------
__global__ __launch_bounds__(128) void interp_kernel(
    const float* __restrict__ x, const float* __restrict__ x_skip)
{
    int f = blockIdx.x;
    int t = threadIdx.x;
    int ia = g_kidx[f*3+0], ib = g_kidx[f*3+1], ic = g_kidx[f*3+2];
    float w0 = g_kw[f*3+0], w1 = g_kw[f*3+1], w2 = g_kw[f*3+2];
    float4 a = ((const float4*)(x + (size_t)ia * C_IN))[t];
    float4 b = ((const float4*)(x + (size_t)ib * C_IN))[t];
    float4 c = ((const float4*)(x + (size_t)ic * C_IN))[t];
    float r[4];
    r[0] = w0*a.x + w1*b.x + w2*c.x;
    r[1] = w0*a.y + w1*b.y + w2*c.y;
    r[2] = w0*a.z + w1*b.z + w2*c.z;
    r[3] = w0*a.w + w1*b.w + w2*c.w;
    __nv_bfloat16 h[4], l[4];
    #pragma unroll
    for (int j = 0; j < 4; ++j) split2(r[j], h[j], l[j]);
    size_t base = (size_t)f * D_IN + t * 4;
    *(uint2*)(g_h0hi + base) = *(uint2*)h;
    *(uint2*)(g_h0lo + base) = *(uint2*)l;
    if (t < C_SKIP / 4) {
        float4 s = ((const float4*)(x_skip + (size_t)f * C_SKIP))[t];
        float sv[4] = {s.x, s.y, s.z, s.w};
        #pragma unroll
        for (int j = 0; j < 4; ++j) split2(sv[j], h[j], l[j]);
        size_t base2 = (size_t)f * D_IN + C_IN + t * 4;
        *(uint2*)(g_h0hi + base2) = *(uint2*)h;
        *(uint2*)(g_h0lo + base2) = *(uint2*)l;
    }
}

// ---------------- W transpose + split: Wt[n][k] = W[k][n] ----------------
__global__ __launch_bounds__(256) void wsplit_kernel(
    const float* __restrict__ W, __nv_bfloat16* __restrict__ hi,
    __nv_bfloat16* __restrict__ lo, int Kd, int N)
{
    int id = blockIdx.x * 256 + threadIdx.x;
    if (id >= N * Kd) return;
    int n = id / Kd, k = id % Kd;
    float v = W[(size_t)k * N + n];
    __nv_bfloat16 h, l;
    split2(v, h, l);
    hi[id] = h; lo[id] = l;
}

// ---------------- h1 -> BN1+ReLU -> bf16 hi/lo split ----------------
__global__ __launch_bounds__(256) void h1split_kernel()
{
    size_t i = (size_t)blockIdx.x * 256 + threadIdx.x;
    int cb = (int)(i & (C_OUT/4 - 1));
    float4 hv = ((const float4*)g_h1)[i];
    float4 av = ((const float4*)g_a1)[cb];
    float4 cv = ((const float4*)g_c1)[cb];
    float v[4];
    v[0] = fmaxf(fmaf(av.x, hv.x, cv.x), 0.0f);
    v[1] = fmaxf(fmaf(av.y, hv.y, cv.y), 0.0f);
    v[2] = fmaxf(fmaf(av.z, hv.z, cv.z), 0.0f);
    v[3] = fmaxf(fmaf(av.w, hv.w, cv.w), 0.0f);
    __nv_bfloat16 h[4], l[4];
    #pragma unroll
    for (int j = 0; j < 4; ++j) split2(v[j], h[j], l[j]);
    *(uint2*)(g_h1hi + i * 4) = *(uint2*)h;
    *(uint2*)(g_h1lo + i * 4) = *(uint2*)l;
}

// ---------------- HMMA split-2 bf16 GEMM (R3 mainloop) + epilogue-fused BN stats ----------------
// C[M,512] = A[M,Kd] @ Wt[512,Kd]^T      (bias dropped: BN shift-invariant)
// CTA tile 128x128, BK=64, 3-stage cp.async pipeline, 8 warps (warp tile 32x64).
// Split-2: D = Ahi*Bhi + Ahi*Blo + Alo*Bhi   (fp32 accum)
#define BK 64
#define REG_BYTES 16384                  // one 128x64 bf16 tile
#define STAGE_BYTES (4 * REG_BYTES)      // Ahi | Alo | Bhi | Blo
#define STAGES 3
#define SM_STAGE_TOT (STAGES * STAGE_BYTES)        // 196608
#define SM_RS   (SM_STAGE_TOT)                     // sred sum 4*128*4 = 2048
#define SM_RQ   (SM_RS + 2048)                     // sred sq 2048
#define GEMM_SMEM (SM_RQ + 2048)                   // 200704

__device__ __forceinline__ uint32_t swoff(int row, int c) {
    return (uint32_t)(row * 128 + ((c ^ (row & 7)) << 4));
}

__global__ __launch_bounds__(256, 1) void gemm_kernel(
    const __nv_bfloat16* __restrict__ Ahi, const __nv_bfloat16* __restrict__ Alo,
    const __nv_bfloat16* __restrict__ Bhi, const __nv_bfloat16* __restrict__ Blo,
    float* __restrict__ C, float* __restrict__ psum, float* __restrict__ psq,
    int Kd, int nchunk)
{
    extern __shared__ __align__(128) char smem[];
    uint32_t sbase = smem_u32(smem);
    int tid  = threadIdx.x;
    int wid  = tid >> 5, lane = tid & 31;
    int m0 = blockIdx.y * 128;
    int n0 = blockIdx.x * 128;

    const __nv_bfloat16* srcs[4] = {
        Ahi + (size_t)m0 * Kd, Alo + (size_t)m0 * Kd,
        Bhi + (size_t)n0 * Kd, Blo + (size_t)n0 * Kd };

    auto issue = [&](int sidx, int k0) {
        uint32_t sb = sbase + (uint32_t)sidx * STAGE_BYTES;
        #pragma unroll
        for (int reg = 0; reg < 4; ++reg) {
            const __nv_bfloat16* src = srcs[reg];
            uint32_t rb = sb + (uint32_t)reg * REG_BYTES;
            #pragma unroll
            for (int it = 0; it < 4; ++it) {
                int chunk = it * 256 + tid;
                int row = chunk >> 3, c = chunk & 7;
                cp16(rb + swoff(row, c), src + (size_t)row * Kd + k0 + c * 8);
            }
        }
    };

    issue(0, 0);        cp_commit();
    issue(1, BK);       cp_commit();

    int wm = wid & 3, wn = wid >> 2;
    int mbase = wm * 32, nbase = wn * 64;
    int sub = lane >> 3, l7 = lane & 7;

    float acc[2][8][4];
    #pragma unroll
    for (int i = 0; i < 2; ++i)
        #pragma unroll
        for (int j = 0; j < 8; ++j)
            #pragma unroll
            for (int q = 0; q < 4; ++q) acc[i][j][q] = 0.0f;

    int arow_l = mbase + ((sub & 1) << 3) + l7;
    int acol_s = (sub >> 1);
    int brow_l = nbase + ((sub >> 1) << 3) + l7;
    int bcol_s = (sub & 1);

    for (int cc = 0; cc < nchunk; ++cc) {
        cp_wait1();
        __syncthreads();
        if (cc + 2 < nchunk) issue((cc + 2) % STAGES, (cc + 2) * BK);
        cp_commit();

        uint32_t bb = sbase + (uint32_t)(cc % STAGES) * STAGE_BYTES;
        #pragma unroll
        for (int ks = 0; ks < 4; ++ks) {
            uint32_t ah[2][4], al[2][4], bh[8][2], bl[8][2];
            int achunk = ks * 2 + acol_s;
            #pragma unroll
            for (int mi = 0; mi < 2; ++mi) {
                uint32_t ao = swoff(arow_l + mi * 16, achunk);
                ldsm4(ah[mi][0], ah[mi][1], ah[mi][2], ah[mi][3], bb + ao);
                ldsm4(al[mi][0], al[mi][1], al[mi][2], al[mi][3], bb + REG_BYTES + ao);
            }
            int bchunk = ks * 2 + bcol_s;
            #pragma unroll
            for (int pi = 0; pi < 4; ++pi) {
                uint32_t bo = swoff(brow_l + pi * 16, bchunk);
                ldsm4(bh[pi*2][0], bh[pi*2][1], bh[pi*2+1][0], bh[pi*2+1][1],
                      bb + 2 * REG_BYTES + bo);
                ldsm4(bl[pi*2][0], bl[pi*2][1], bl[pi*2+1][0], bl[pi*2+1][1],
                      bb + 3 * REG_BYTES + bo);
            }
            #pragma unroll
            for (int mi = 0; mi < 2; ++mi)
                #pragma unroll
                for (int ni = 0; ni < 8; ++ni)
                    mma16816(acc[mi][ni], ah[mi], bh[ni]);
            #pragma unroll
            for (int mi = 0; mi < 2; ++mi)
                #pragma unroll
                for (int ni = 0; ni < 8; ++ni)
                    mma16816(acc[mi][ni], ah[mi], bl[ni]);
            #pragma unroll
            for (int mi = 0; mi < 2; ++mi)
                #pragma unroll
                for (int ni = 0; ni < 8; ++ni)
                    mma16816(acc[mi][ni], al[mi], bh[ni]);
        }
    }

    // ---- epilogue: fp32 store (no bias) ----
    int grow = m0 + mbase + (lane >> 2);
    int gcol0 = n0 + nbase + (lane & 3) * 2;
    #pragma unroll
    for (int ni = 0; ni < 8; ++ni) {
        int col = gcol0 + ni * 8;
        #pragma unroll
        for (int mi = 0; mi < 2; ++mi) {
            int r = grow + mi * 16;
            *(float2*)(C + (size_t)r * C_OUT + col)       = make_float2(acc[mi][ni][0], acc[mi][ni][1]);
            *(float2*)(C + (size_t)(r + 8) * C_OUT + col) = make_float2(acc[mi][ni][2], acc[mi][ni][3]);
        }
    }

    // ---- fused column stats from accumulators (deterministic) ----
    float scol[16], qcol[16];
    #pragma unroll
    for (int ni = 0; ni < 8; ++ni) {
        #pragma unroll
        for (int ch = 0; ch < 2; ++ch) {
            float v0 = acc[0][ni][ch],     v1 = acc[0][ni][ch + 2];
            float v2 = acc[1][ni][ch],     v3 = acc[1][ni][ch + 2];
            scol[ni*2+ch] = (v0 + v1) + (v2 + v3);
            qcol[ni*2+ch] = (v0*v0 + v1*v1) + (v2*v2 + v3*v3);
        }
    }
    #pragma unroll
    for (int t = 0; t < 16; ++t) {
        #pragma unroll
        for (int m = 4; m <= 16; m <<= 1) {
            scol[t] += __shfl_xor_sync(0xFFFFFFFFu, scol[t], m);
            qcol[t] += __shfl_xor_sync(0xFFFFFFFFu, qcol[t], m);
        }
    }
    float* sred_s = (float*)(smem + SM_RS);
    float* sred_q = (float*)(smem + SM_RQ);
    __syncthreads();   // smem stage reuse safety
    if (lane < 4) {
        #pragma unroll
        for (int ni = 0; ni < 8; ++ni) {
            #pragma unroll
            for (int ch = 0; ch < 2; ++ch) {
                int cidx = wn * 64 + lane * 2 + ni * 8 + ch;
                sred_s[wm * 128 + cidx] = scol[ni*2+ch];
                sred_q[wm * 128 + cidx] = qcol[ni*2+ch];
            }
        }
    }
    __syncthreads();
    if (tid < 128) {
        float s = ((sred_s[tid] + sred_s[128 + tid]) + (sred_s[256 + tid] + sred_s[384 + tid]));
        float q = ((sred_q[tid] + sred_q[128 + tid]) + (sred_q[256 + tid] + sred_q[384 + tid]));
        psum[(size_t)blockIdx.y * C_OUT + n0 + tid] = s;
        psq [(size_t)blockIdx.y * C_OUT + n0 + tid] = q;
    }
}

// ---------------- finalize: fold 512 m-block partials -> affine coefs ----------------
__global__ __launch_bounds__(128) void finalize_kernel(
    const float* __restrict__ g, const float* __restrict__ be,
    float* __restrict__ a, float* __restrict__ c)
{
    int ch = blockIdx.x * 128 + threadIdx.x;
    float s = 0, q = 0;
    for (int p = 0; p < NMBLK; ++p) {
        s += g_psum[p * C_OUT + ch];
        q += g_psq [p * C_OUT + ch];
    }
    float mu  = s * (1.0f / NF_TOT);
    float var = q * (1.0f / NF_TOT) - mu * mu;
    float av  = g[ch] * rsqrtf(var + BN_EPS);
    a[ch] = av;
    c[ch] = be[ch] - mu * av;
}

// ---------------- final BN2 + ReLU -> out ----------------
__global__ __launch_bounds__(256) void apply_out_kernel(
    const float* __restrict__ H, float* __restrict__ out)
{
    size_t i = (size_t)blockIdx.x * 256 + threadIdx.x;
    int cb = (int)(i & (C_OUT/4 - 1));
    float4 h  = ((const float4*)H)[i];
    float4 av = ((const float4*)g_a2)[cb];
    float4 cv = ((const float4*)g_c2)[cb];
    float4 r;
    r.x = fmaxf(fmaf(av.x, h.x, cv.x), 0.0f);
    r.y = fmaxf(fmaf(av.y, h.y, cv.y), 0.0f);
    r.z = fmaxf(fmaf(av.z, h.z, cv.z), 0.0f);
    r.w = fmaxf(fmaf(av.w, h.w, cv.w), 0.0f);
    ((float4*)out)[i] = r;
}

// ---------------- tuple extras ----------------
__global__ __launch_bounds__(256) void extras_kernel(
    const float* __restrict__ pos_skip, float* __restrict__ out, int mode)
{
    int i = blockIdx.x * 256 + threadIdx.x;
    const size_t baseH = (size_t)NF_TOT * C_OUT;
    if (i < NF_TOT * 3) out[baseH + i] = pos_skip[i];
    if (i < NF_TOT) {
        if (mode == 1)
            out[baseH + NF_TOT*3 + i] = (float)(i >> 12);
        else if (mode == 2)
            ((long long*)(out + baseH + NF_TOT*3))[i] = (long long)(i >> 12);
    }
}

// ---------------- host ----------------
extern "C" void kernel_launch(void* const* d_in, const int* in_sizes, int n_in,
                              void* d_out, int out_size)
{
    const float* x        = (const float*)d_in[0];
    const float* pos      = (const float*)d_in[1];
    const float* x_skip   = (const float*)d_in[3];
    const float* pos_skip = (const float*)d_in[4];
    const float* W1  = (const float*)d_in[6];
    const float* g1  = (const float*)d_in[8];
    const float* be1 = (const float*)d_in[9];
    const float* W2  = (const float*)d_in[10];
    const float* g2  = (const float*)d_in[12];
    const float* be2 = (const float*)d_in[13];
    float* out = (float*)d_out;

    float *p_h1, *p_h2, *p_a1, *p_c1, *p_a2, *p_c2, *p_psum, *p_psq;
    cudaGetSymbolAddress((void**)&p_h1, g_h1);
    cudaGetSymbolAddress((void**)&p_h2, g_h2);
    cudaGetSymbolAddress((void**)&p_a1, g_a1);
    cudaGetSymbolAddress((void**)&p_c1, g_c1);
    cudaGetSymbolAddress((void**)&p_a2, g_a2);
    cudaGetSymbolAddress((void**)&p_c2, g_c2);
    cudaGetSymbolAddress((void**)&p_psum, g_psum);
    cudaGetSymbolAddress((void**)&p_psq, g_psq);
    int *p_kidx; float *p_kw;
    cudaGetSymbolAddress((void**)&p_kidx, g_kidx);
    cudaGetSymbolAddress((void**)&p_kw,   g_kw);
    __nv_bfloat16 *p_h0hi, *p_h0lo, *p_h1hi, *p_h1lo, *p_w1thi, *p_w1tlo, *p_w2thi, *p_w2tlo;
    cudaGetSymbolAddress((void**)&p_h0hi, g_h0hi);
    cudaGetSymbolAddress((void**)&p_h0lo, g_h0lo);
    cudaGetSymbolAddress((void**)&p_h1hi, g_h1hi);
    cudaGetSymbolAddress((void**)&p_h1lo, g_h1lo);
    cudaGetSymbolAddress((void**)&p_w1thi, g_w1thi);
    cudaGetSymbolAddress((void**)&p_w1tlo, g_w1tlo);
    cudaGetSymbolAddress((void**)&p_w2thi, g_w2thi);
    cudaGetSymbolAddress((void**)&p_w2tlo, g_w2tlo);

    cudaFuncSetAttribute(gemm_kernel, cudaFuncAttributeMaxDynamicSharedMemorySize, GEMM_SMEM);

    // weight prep
    wsplit_kernel<<<(C_OUT * D_IN + 255) / 256, 256>>>(W1, p_w1thi, p_w1tlo, D_IN, C_OUT);
    wsplit_kernel<<<(C_OUT * C_OUT + 255) / 256, 256>>>(W2, p_w2thi, p_w2tlo, C_OUT, C_OUT);
    // 1) kNN
    knn_kernel<<<NF_TOT / 256, 256>>>(pos, pos_skip, p_kidx, p_kw);
    // 2) interpolate + concat -> h0 hi/lo
    interp_kernel<<<NF_TOT, 128>>>(x, x_skip);
    // 3) GEMM1 -> h1 fp32 + fused BN1 stats
    {
        dim3 grid(C_OUT / 128, NF_TOT / 128);
        gemm_kernel<<<grid, 256, GEMM_SMEM>>>(p_h0hi, p_h0lo, p_w1thi, p_w1tlo,
                                              p_h1, p_psum, p_psq, D_IN, D_IN / BK);
    }
    finalize_kernel<<<C_OUT / 128, 128>>>(g1, be1, p_a1, p_c1);
    // 4) BN1+ReLU+split -> h1 hi/lo
    h1split_kernel<<<(NF_TOT * (C_OUT / 4)) / 256, 256>>>();
    // 5) GEMM2 -> h2 fp32 + fused BN2 stats
    {
        dim3 grid(C_OUT / 128, NF_TOT / 128);
        gemm_kernel<<<grid, 256, GEMM_SMEM>>>(p_h1hi, p_h1lo, p_w2thi, p_w2tlo,
                                              p_h2, p_psum, p_psq, C_OUT, C_OUT / BK);
    }
    finalize_kernel<<<C_OUT / 128, 128>>>(g2, be2, p_a2, p_c2);
    // 6) BN2 + ReLU -> out
    apply_out_kernel<<<(NF_TOT * (C_OUT / 4)) / 256, 256>>>(p_h2, out);
    // 7) tuple extras
    {
        long long baseH = (long long)NF_TOT * C_OUT;
        long long rem = (long long)out_size - baseH - (long long)NF_TOT * 3;
        int mode = 0;
        if (rem >= 2LL * NF_TOT)      mode = 2;
        else if (rem >= (long long)NF_TOT) mode = 1;
        if ((long long)out_size >= baseH + (long long)NF_TOT * 3)
            extras_kernel<<<(NF_TOT * 3 + 255) / 256, 256>>>(pos_skip, out, mode);
    }
}

// round 7
// speedup vs baseline: 1.1562x; 1.0260x over previous
#include <cuda_runtime.h>
#include <cuda_bf16.h>
#include <cstdint>

// ---------------- problem constants ----------------
#define BATCHES   16
#define NC_PER    1024
#define NF_PER    4096
#define NC_TOT    (BATCHES * NC_PER)   // 16384
#define NF_TOT    (BATCHES * NF_PER)   // 65536
#define C_IN      512
#define C_SKIP    256
#define D_IN      (C_IN + C_SKIP)      // 768
#define C_OUT     512
#define BN_EPS    1e-5f
#define PSTATS    256

// ---------------- device scratch ----------------
__device__ __align__(128) __nv_bfloat16 g_h0hi[(size_t)NF_TOT * D_IN];
__device__ __align__(128) __nv_bfloat16 g_h0lo[(size_t)NF_TOT * D_IN];
__device__ __align__(128) float         g_h1[(size_t)NF_TOT * C_OUT];
__device__ __align__(128) float         g_h2[(size_t)NF_TOT * C_OUT];
__device__ __align__(128) __nv_bfloat16 g_h1hi[(size_t)NF_TOT * C_OUT];
__device__ __align__(128) __nv_bfloat16 g_h1lo[(size_t)NF_TOT * C_OUT];
__device__ __align__(128) __nv_bfloat16 g_w1thi[(size_t)C_OUT * D_IN];
__device__ __align__(128) __nv_bfloat16 g_w1tlo[(size_t)C_OUT * D_IN];
__device__ __align__(128) __nv_bfloat16 g_w2thi[(size_t)C_OUT * C_OUT];
__device__ __align__(128) __nv_bfloat16 g_w2tlo[(size_t)C_OUT * C_OUT];
__device__ int   g_kidx[(size_t)NF_TOT * 3];
__device__ float g_kw[(size_t)NF_TOT * 3];
__device__ float g_psum[PSTATS * C_OUT];
__device__ float g_psq[PSTATS * C_OUT];
__device__ float g_a1[C_OUT], g_c1[C_OUT], g_a2[C_OUT], g_c2[C_OUT];

// ---------------- helpers ----------------
__device__ __forceinline__ uint32_t smem_u32(const void* p) {
    uint32_t a;
    asm("{ .reg .u64 t; cvta.to.shared.u64 t, %1; cvt.u32.u64 %0, t; }" : "=r"(a) : "l"(p));
    return a;
}
__device__ __forceinline__ void cp16(uint32_t dst, const void* src) {
    asm volatile("cp.async.cg.shared.global [%0], [%1], 16;" :: "r"(dst), "l"(src));
}
__device__ __forceinline__ void cp_commit() {
    asm volatile("cp.async.commit_group;" ::: "memory");
}
__device__ __forceinline__ void cp_wait1() {
    asm volatile("cp.async.wait_group 1;" ::: "memory");
}
__device__ __forceinline__ void cp_wait0() {
    asm volatile("cp.async.wait_group 0;" ::: "memory");
}
__device__ __forceinline__ void ldsm4(uint32_t& r0, uint32_t& r1, uint32_t& r2, uint32_t& r3, uint32_t addr) {
    asm volatile("ldmatrix.sync.aligned.m8n8.x4.shared.b16 {%0,%1,%2,%3}, [%4];"
                 : "=r"(r0), "=r"(r1), "=r"(r2), "=r"(r3) : "r"(addr));
}
__device__ __forceinline__ void mma16816(float* c, const uint32_t* a, const uint32_t* b) {
    asm volatile("mma.sync.aligned.m16n8k16.row.col.f32.bf16.bf16.f32 "
                 "{%0,%1,%2,%3}, {%4,%5,%6,%7}, {%8,%9}, {%0,%1,%2,%3};"
                 : "+f"(c[0]), "+f"(c[1]), "+f"(c[2]), "+f"(c[3])
                 : "r"(a[0]), "r"(a[1]), "r"(a[2]), "r"(a[3]), "r"(b[0]), "r"(b[1]));
}
__device__ __forceinline__ void split2(float v, __nv_bfloat16& h, __nv_bfloat16& l) {
    h = __float2bfloat16(v);
    l = __float2bfloat16(v - __bfloat162float(h));
}

// ---------------- kNN (K=3) ----------------
__global__ __launch_bounds__(256) void knn_kernel(
    const float* __restrict__ pos, const float* __restrict__ pos_skip,
    int* __restrict__ idx_out, float* __restrict__ w_out)
{
    __shared__ float sx[NC_PER], sy[NC_PER], sz[NC_PER], sn[NC_PER];
    int blk = blockIdx.x;
    int b = blk >> 4;
    const float* pc = pos + (size_t)b * NC_PER * 3;
    for (int i = threadIdx.x; i < NC_PER; i += 256) {
        float px = pc[i*3+0], py = pc[i*3+1], pz = pc[i*3+2];
        sx[i] = px; sy[i] = py; sz[i] = pz;
        sn[i] = px*px + py*py + pz*pz;
    }
    __syncthreads();
    int f = blk * 256 + threadIdx.x;
    float fx = pos_skip[f*3+0], fy = pos_skip[f*3+1], fz = pos_skip[f*3+2];
    float fn = fx*fx + fy*fy + fz*fz;
    float d0 = 3.4e38f, d1 = 3.4e38f, d2 = 3.4e38f;
    int   i0 = 0, i1 = 0, i2 = 0;
    for (int c = 0; c < NC_PER; ++c) {
        float dot = fx*sx[c] + fy*sy[c] + fz*sz[c];
        float dd  = fn + sn[c] - 2.0f*dot;
        if (dd < d2) {
            if (dd < d1) {
                if (dd < d0) { d2=d1; i2=i1; d1=d0; i1=i0; d0=dd; i0=c; }
                else         { d2=d1; i2=i1; d1=dd; i1=c; }
            } else           { d2=dd; i2=c; }
        }
    }
    float w0 = 1.0f / fmaxf(d0, 1e-16f);
    float w1 = 1.0f / fmaxf(d1, 1e-16f);
    float w2 = 1.0f / fmaxf(d2, 1e-16f);
    float inv = 1.0f / (w0 + w1 + w2);
    idx_out[f*3+0] = b * NC_PER + i0;
    idx_out[f*3+1] = b * NC_PER + i1;
    idx_out[f*3+2] = b * NC_PER + i2;
    w_out[f*3+0] = w0 * inv;
    w_out[f*3+1] = w1 * inv;
    w_out[f*3+2] = w2 * inv;
}

// ---------------- interpolate + concat -> bf16 hi/lo h0 ----------------
__global__ __launch_bounds__(128) void interp_kernel(
    const float* __restrict__ x, const float* __restrict__ x_skip)
{
    int f = blockIdx.x;
    int t = threadIdx.x;
    int ia = g_kidx[f*3+0], ib = g_kidx[f*3+1], ic = g_kidx[f*3+2];
    float w0 = g_kw[f*3+0], w1 = g_kw[f*3+1], w2 = g_kw[f*3+2];
    float4 a = ((const float4*)(x + (size_t)ia * C_IN))[t];
    float4 b = ((const float4*)(x + (size_t)ib * C_IN))[t];
    float4 c = ((const float4*)(x + (size_t)ic * C_IN))[t];
    float r[4];
    r[0] = w0*a.x + w1*b.x + w2*c.x;
    r[1] = w0*a.y + w1*b.y + w2*c.y;
    r[2] = w0*a.z + w1*b.z + w2*c.z;
    r[3] = w0*a.w + w1*b.w + w2*c.w;
    __nv_bfloat16 h[4], l[4];
    #pragma unroll
    for (int j = 0; j < 4; ++j) split2(r[j], h[j], l[j]);
    size_t base = (size_t)f * D_IN + t * 4;
    *(uint2*)(g_h0hi + base) = *(uint2*)h;
    *(uint2*)(g_h0lo + base) = *(uint2*)l;
    if (t < C_SKIP / 4) {
        float4 s = ((const float4*)(x_skip + (size_t)f * C_SKIP))[t];
        float sv[4] = {s.x, s.y, s.z, s.w};
        #pragma unroll
        for (int j = 0; j < 4; ++j) split2(sv[j], h[j], l[j]);
        size_t base2 = (size_t)f * D_IN + C_IN + t * 4;
        *(uint2*)(g_h0hi + base2) = *(uint2*)h;
        *(uint2*)(g_h0lo + base2) = *(uint2*)l;
    }
}

// ---------------- W transpose + split: Wt[n][k] = W[k][n] ----------------
__global__ __launch_bounds__(256) void wsplit_kernel(
    const float* __restrict__ W, __nv_bfloat16* __restrict__ hi,
    __nv_bfloat16* __restrict__ lo, int Kd, int N)
{
    int id = blockIdx.x * 256 + threadIdx.x;
    if (id >= N * Kd) return;
    int n = id / Kd, k = id % Kd;
    float v = W[(size_t)k * N + n];
    __nv_bfloat16 h, l;
    split2(v, h, l);
    hi[id] = h; lo[id] = l;
}

// ---------------- h1 -> BN1+ReLU -> bf16 hi/lo split ----------------
__global__ __launch_bounds__(256) void h1split_kernel()
{
    size_t i = (size_t)blockIdx.x * 256 + threadIdx.x;
    int cb = (int)(i & (C_OUT/4 - 1));
    float4 hv = ((const float4*)g_h1)[i];
    float4 av = ((const float4*)g_a1)[cb];
    float4 cv = ((const float4*)g_c1)[cb];
    float v[4];
    v[0] = fmaxf(fmaf(av.x, hv.x, cv.x), 0.0f);
    v[1] = fmaxf(fmaf(av.y, hv.y, cv.y), 0.0f);
    v[2] = fmaxf(fmaf(av.z, hv.z, cv.z), 0.0f);
    v[3] = fmaxf(fmaf(av.w, hv.w, cv.w), 0.0f);
    __nv_bfloat16 h[4], l[4];
    #pragma unroll
    for (int j = 0; j < 4; ++j) split2(v[j], h[j], l[j]);
    *(uint2*)(g_h1hi + i * 4) = *(uint2*)h;
    *(uint2*)(g_h1lo + i * 4) = *(uint2*)l;
}

// ---------------- HMMA split-2 bf16 GEMM: 128(M)x256(N) tile, 512 thr, 2-stage ----------------
// C[M,512] = A[M,Kd] @ Wt[512,Kd]^T       (bias dropped: BN shift-invariant)
// Split-2: D = Ahi*Bhi + Alo*Bhi + Ahi*Blo   (fp32 accum)
#define BK 64
#define A_BYTES 16384                    // 128x64 bf16
#define B_BYTES 32768                    // 256x64 bf16
#define STAGE_BYTES (2*A_BYTES + 2*B_BYTES)   // 98304
#define GEMM_SMEM (2 * STAGE_BYTES)           // 196608

__device__ __forceinline__ uint32_t swoff(int row, int c) {
    return (uint32_t)(row * 128 + ((c ^ (row & 7)) << 4));
}

__global__ __launch_bounds__(512, 1) void gemm_kernel(
    const __nv_bfloat16* __restrict__ Ahi, const __nv_bfloat16* __restrict__ Alo,
    const __nv_bfloat16* __restrict__ Bhi, const __nv_bfloat16* __restrict__ Blo,
    float* __restrict__ C, int Kd, int nchunk)
{
    extern __shared__ __align__(128) char smem[];
    uint32_t sbase = smem_u32(smem);
    int tid  = threadIdx.x;
    int wid  = tid >> 5, lane = tid & 31;
    int m0 = blockIdx.y * 128;
    int n0 = blockIdx.x * 256;

    const __nv_bfloat16* asrc[2] = { Ahi + (size_t)m0 * Kd, Alo + (size_t)m0 * Kd };
    const __nv_bfloat16* bsrc[2] = { Bhi + (size_t)n0 * Kd, Blo + (size_t)n0 * Kd };

    auto issue = [&](int sidx, int k0) {
        uint32_t sb = sbase + (uint32_t)sidx * STAGE_BYTES;
        #pragma unroll
        for (int reg = 0; reg < 2; ++reg) {          // A hi/lo: 128 rows
            uint32_t rb = sb + (uint32_t)reg * A_BYTES;
            const __nv_bfloat16* src = asrc[reg];
            #pragma unroll
            for (int it = 0; it < 2; ++it) {
                int chunk = it * 512 + tid;
                int row = chunk >> 3, c = chunk & 7;
                cp16(rb + swoff(row, c), src + (size_t)row * Kd + k0 + c * 8);
            }
        }
        #pragma unroll
        for (int reg = 0; reg < 2; ++reg) {          // B hi/lo: 256 rows
            uint32_t rb = sb + 2 * A_BYTES + (uint32_t)reg * B_BYTES;
            const __nv_bfloat16* src = bsrc[reg];
            #pragma unroll
            for (int it = 0; it < 4; ++it) {
                int chunk = it * 512 + tid;
                int row = chunk >> 3, c = chunk & 7;
                cp16(rb + swoff(row, c), src + (size_t)row * Kd + k0 + c * 8);
            }
        }
    };

    issue(0, 0);
    cp_commit();

    // warp tiling: 4 (M) x 4 (N) warps; warp tile 32(M) x 64(N)
    int wm = wid & 3, wn = wid >> 2;
    int mbase = wm * 32, nbase = wn * 64;
    int sub = lane >> 3, l7 = lane & 7;

    float acc[2][8][4];
    #pragma unroll
    for (int i = 0; i < 2; ++i)
        #pragma unroll
        for (int j = 0; j < 8; ++j)
            #pragma unroll
            for (int q = 0; q < 4; ++q) acc[i][j][q] = 0.0f;

    int arow_l = mbase + ((sub & 1) << 3) + l7;
    int acol_s = (sub >> 1);
    int brow_l = nbase + ((sub >> 1) << 3) + l7;
    int bcol_s = (sub & 1);

    for (int cc = 0; cc < nchunk; ++cc) {
        if (cc + 1 < nchunk) {
            issue((cc + 1) & 1, (cc + 1) * BK);   // buffer freed at end of iter cc-1
            cp_commit();
            cp_wait1();                            // chunk cc resident; cc+1 in flight
        } else {
            cp_wait0();
        }
        __syncthreads();

        uint32_t bb = sbase + (uint32_t)(cc & 1) * STAGE_BYTES;
        #pragma unroll
        for (int ks = 0; ks < 4; ++ks) {
            int achunk = ks * 2 + acol_s;
            int bchunk = ks * 2 + bcol_s;
            uint32_t ah[2][4], bh[8][2];
            #pragma unroll
            for (int mi = 0; mi < 2; ++mi) {
                uint32_t ao = swoff(arow_l + mi * 16, achunk);
                ldsm4(ah[mi][0], ah[mi][1], ah[mi][2], ah[mi][3], bb + ao);
            }
            #pragma unroll
            for (int pi = 0; pi < 4; ++pi) {
                uint32_t bo = swoff(brow_l + pi * 16, bchunk);
                ldsm4(bh[pi*2][0], bh[pi*2][1], bh[pi*2+1][0], bh[pi*2+1][1],
                      bb + 2 * A_BYTES + bo);
            }
            // P1: Ahi * Bhi
            #pragma unroll
            for (int mi = 0; mi < 2; ++mi)
                #pragma unroll
                for (int ni = 0; ni < 8; ++ni)
                    mma16816(acc[mi][ni], ah[mi], bh[ni]);
            // P3: Alo * Bhi   (load al, reuse bh)
            {
                uint32_t al[2][4];
                #pragma unroll
                for (int mi = 0; mi < 2; ++mi) {
                    uint32_t ao = swoff(arow_l + mi * 16, achunk);
                    ldsm4(al[mi][0], al[mi][1], al[mi][2], al[mi][3], bb + A_BYTES + ao);
                }
                #pragma unroll
                for (int mi = 0; mi < 2; ++mi)
                    #pragma unroll
                    for (int ni = 0; ni < 8; ++ni)
                        mma16816(acc[mi][ni], al[mi], bh[ni]);
            }
            // P2: Ahi * Blo   (load bl over bh, reuse ah)
            #pragma unroll
            for (int pi = 0; pi < 4; ++pi) {
                uint32_t bo = swoff(brow_l + pi * 16, bchunk);
                ldsm4(bh[pi*2][0], bh[pi*2][1], bh[pi*2+1][0], bh[pi*2+1][1],
                      bb + 2 * A_BYTES + B_BYTES + bo);
            }
            #pragma unroll
            for (int mi = 0; mi < 2; ++mi)
                #pragma unroll
                for (int ni = 0; ni < 8; ++ni)
                    mma16816(acc[mi][ni], ah[mi], bh[ni]);
        }
        __syncthreads();   // all warps done with this buffer before it is re-issued
    }

    // ---- epilogue: fp32 store ----
    int grow = m0 + mbase + (lane >> 2);
    int gcol0 = n0 + nbase + (lane & 3) * 2;
    #pragma unroll
    for (int ni = 0; ni < 8; ++ni) {
        int col = gcol0 + ni * 8;
        #pragma unroll
        for (int mi = 0; mi < 2; ++mi) {
            int r = grow + mi * 16;
            *(float2*)(C + (size_t)r * C_OUT + col)       = make_float2(acc[mi][ni][0], acc[mi][ni][1]);
            *(float2*)(C + (size_t)(r + 8) * C_OUT + col) = make_float2(acc[mi][ni][2], acc[mi][ni][3]);
        }
    }
}

// ---------------- BN stats (two-stage, deterministic) ----------------
__global__ __launch_bounds__(256) void stats_kernel(const float* __restrict__ H)
{
    int r0 = blockIdx.x * 256;
    int t = threadIdx.x;
    float s0 = 0, q0 = 0, s1 = 0, q1 = 0;
    for (int r = r0; r < r0 + 256; ++r) {
        float v0 = H[(size_t)r * C_OUT + t];
        float v1 = H[(size_t)r * C_OUT + t + 256];
        s0 += v0; q0 += v0*v0;
        s1 += v1; q1 += v1*v1;
    }
    g_psum[blockIdx.x * C_OUT + t]       = s0;
    g_psq [blockIdx.x * C_OUT + t]       = q0;
    g_psum[blockIdx.x * C_OUT + t + 256] = s1;
    g_psq [blockIdx.x * C_OUT + t + 256] = q1;
}

__global__ __launch_bounds__(128) void finalize_kernel(
    const float* __restrict__ g, const float* __restrict__ be,
    float* __restrict__ a, float* __restrict__ c)
{
    int ch = blockIdx.x * 128 + threadIdx.x;
    float s = 0, q = 0;
    for (int p = 0; p < PSTATS; ++p) {
        s += g_psum[p * C_OUT + ch];
        q += g_psq [p * C_OUT + ch];
    }
    float mu  = s * (1.0f / NF_TOT);
    float var = q * (1.0f / NF_TOT) - mu * mu;
    float av  = g[ch] * rsqrtf(var + BN_EPS);
    a[ch] = av;
    c[ch] = be[ch] - mu * av;
}

// ---------------- final BN2 + ReLU -> out ----------------
__global__ __launch_bounds__(256) void apply_out_kernel(
    const float* __restrict__ H, float* __restrict__ out)
{
    size_t i = (size_t)blockIdx.x * 256 + threadIdx.x;
    int cb = (int)(i & (C_OUT/4 - 1));
    float4 h  = ((const float4*)H)[i];
    float4 av = ((const float4*)g_a2)[cb];
    float4 cv = ((const float4*)g_c2)[cb];
    float4 r;
    r.x = fmaxf(fmaf(av.x, h.x, cv.x), 0.0f);
    r.y = fmaxf(fmaf(av.y, h.y, cv.y), 0.0f);
    r.z = fmaxf(fmaf(av.z, h.z, cv.z), 0.0f);
    r.w = fmaxf(fmaf(av.w, h.w, cv.w), 0.0f);
    ((float4*)out)[i] = r;
}

// ---------------- tuple extras ----------------
__global__ __launch_bounds__(256) void extras_kernel(
    const float* __restrict__ pos_skip, float* __restrict__ out, int mode)
{
    int i = blockIdx.x * 256 + threadIdx.x;
    const size_t baseH = (size_t)NF_TOT * C_OUT;
    if (i < NF_TOT * 3) out[baseH + i] = pos_skip[i];
    if (i < NF_TOT) {
        if (mode == 1)
            out[baseH + NF_TOT*3 + i] = (float)(i >> 12);
        else if (mode == 2)
            ((long long*)(out + baseH + NF_TOT*3))[i] = (long long)(i >> 12);
    }
}

// ---------------- host ----------------
extern "C" void kernel_launch(void* const* d_in, const int* in_sizes, int n_in,
                              void* d_out, int out_size)
{
    const float* x        = (const float*)d_in[0];
    const float* pos      = (const float*)d_in[1];
    const float* x_skip   = (const float*)d_in[3];
    const float* pos_skip = (const float*)d_in[4];
    const float* W1  = (const float*)d_in[6];
    const float* g1  = (const float*)d_in[8];
    const float* be1 = (const float*)d_in[9];
    const float* W2  = (const float*)d_in[10];
    const float* g2  = (const float*)d_in[12];
    const float* be2 = (const float*)d_in[13];
    float* out = (float*)d_out;

    float *p_h1, *p_h2, *p_a1, *p_c1, *p_a2, *p_c2;
    cudaGetSymbolAddress((void**)&p_h1, g_h1);
    cudaGetSymbolAddress((void**)&p_h2, g_h2);
    cudaGetSymbolAddress((void**)&p_a1, g_a1);
    cudaGetSymbolAddress((void**)&p_c1, g_c1);
    cudaGetSymbolAddress((void**)&p_a2, g_a2);
    cudaGetSymbolAddress((void**)&p_c2, g_c2);
    int *p_kidx; float *p_kw;
    cudaGetSymbolAddress((void**)&p_kidx, g_kidx);
    cudaGetSymbolAddress((void**)&p_kw,   g_kw);
    __nv_bfloat16 *p_h0hi, *p_h0lo, *p_h1hi, *p_h1lo, *p_w1thi, *p_w1tlo, *p_w2thi, *p_w2tlo;
    cudaGetSymbolAddress((void**)&p_h0hi, g_h0hi);
    cudaGetSymbolAddress((void**)&p_h0lo, g_h0lo);
    cudaGetSymbolAddress((void**)&p_h1hi, g_h1hi);
    cudaGetSymbolAddress((void**)&p_h1lo, g_h1lo);
    cudaGetSymbolAddress((void**)&p_w1thi, g_w1thi);
    cudaGetSymbolAddress((void**)&p_w1tlo, g_w1tlo);
    cudaGetSymbolAddress((void**)&p_w2thi, g_w2thi);
    cudaGetSymbolAddress((void**)&p_w2tlo, g_w2tlo);

    cudaFuncSetAttribute(gemm_kernel, cudaFuncAttributeMaxDynamicSharedMemorySize, GEMM_SMEM);

    // weight prep
    wsplit_kernel<<<(C_OUT * D_IN + 255) / 256, 256>>>(W1, p_w1thi, p_w1tlo, D_IN, C_OUT);
    wsplit_kernel<<<(C_OUT * C_OUT + 255) / 256, 256>>>(W2, p_w2thi, p_w2tlo, C_OUT, C_OUT);
    // 1) kNN
    knn_kernel<<<NF_TOT / 256, 256>>>(pos, pos_skip, p_kidx, p_kw);
    // 2) interpolate + concat -> h0 hi/lo
    interp_kernel<<<NF_TOT, 128>>>(x, x_skip);
    // 3) GEMM1 -> h1 fp32
    {
        dim3 grid(C_OUT / 256, NF_TOT / 128);
        gemm_kernel<<<grid, 512, GEMM_SMEM>>>(p_h0hi, p_h0lo, p_w1thi, p_w1tlo,
                                              p_h1, D_IN, D_IN / BK);
    }
    // 4) BN1 stats + affine coefs
    stats_kernel<<<NF_TOT / 256, 256>>>(p_h1);
    finalize_kernel<<<C_OUT / 128, 128>>>(g1, be1, p_a1, p_c1);
    // 5) BN1+ReLU+split -> h1 hi/lo
    h1split_kernel<<<(NF_TOT * (C_OUT / 4)) / 256, 256>>>();
    // 6) GEMM2 -> h2 fp32
    {
        dim3 grid(C_OUT / 256, NF_TOT / 128);
        gemm_kernel<<<grid, 512, GEMM_SMEM>>>(p_h1hi, p_h1lo, p_w2thi, p_w2tlo,
                                              p_h2, C_OUT, C_OUT / BK);
    }
    // 7) BN2 stats + affine coefs
    stats_kernel<<<NF_TOT / 256, 256>>>(p_h2);
    finalize_kernel<<<C_OUT / 128, 128>>>(g2, be2, p_a2, p_c2);
    // 8) BN2 + ReLU -> out
    apply_out_kernel<<<(NF_TOT * (C_OUT / 4)) / 256, 256>>>(p_h2, out);
    // 9) tuple extras
    {
        long long baseH = (long long)NF_TOT * C_OUT;
        long long rem = (long long)out_size - baseH - (long long)NF_TOT * 3;
        int mode = 0;
        if (rem >= 2LL * NF_TOT)      mode = 2;
        else if (rem >= (long long)NF_TOT) mode = 1;
        if ((long long)out_size >= baseH + (long long)NF_TOT * 3)
            extras_kernel<<<(NF_TOT * 3 + 255) / 256, 256>>>(pos_skip, out, mode);
    }
}

// round 8
// speedup vs baseline: 1.4395x; 1.2450x over previous
#include <cuda_runtime.h>
#include <cuda_fp16.h>
#include <cstdint>

// ---------------- problem constants ----------------
#define BATCHES   16
#define NC_PER    1024
#define NF_PER    4096
#define NC_TOT    (BATCHES * NC_PER)   // 16384
#define NF_TOT    (BATCHES * NF_PER)   // 65536
#define C_IN      512
#define C_SKIP    256
#define D_IN      (C_IN + C_SKIP)      // 768
#define C_OUT     512
#define BN_EPS    1e-5f
#define PSTATS    256

// ---------------- device scratch ----------------
__device__ __align__(128) __half g_h0hi[(size_t)NF_TOT * D_IN];
__device__ __align__(128) __half g_h0lo[(size_t)NF_TOT * D_IN];
__device__ __align__(128) float  g_h1[(size_t)NF_TOT * C_OUT];
__device__ __align__(128) float  g_h2[(size_t)NF_TOT * C_OUT];
__device__ __align__(128) __half g_h1hi[(size_t)NF_TOT * C_OUT];
__device__ __align__(128) __half g_h1lo[(size_t)NF_TOT * C_OUT];
__device__ __align__(128) __half g_w1t[(size_t)C_OUT * D_IN];
__device__ __align__(128) __half g_w2t[(size_t)C_OUT * C_OUT];
__device__ int   g_kidx[(size_t)NF_TOT * 3];
__device__ float g_kw[(size_t)NF_TOT * 3];
__device__ float g_psum[PSTATS * C_OUT];
__device__ float g_psq[PSTATS * C_OUT];
__device__ float g_a1[C_OUT], g_c1[C_OUT], g_a2[C_OUT], g_c2[C_OUT];

// ---------------- helpers ----------------
__device__ __forceinline__ uint32_t smem_u32(const void* p) {
    uint32_t a;
    asm("{ .reg .u64 t; cvta.to.shared.u64 t, %1; cvt.u32.u64 %0, t; }" : "=r"(a) : "l"(p));
    return a;
}
__device__ __forceinline__ void cp16(uint32_t dst, const void* src) {
    asm volatile("cp.async.cg.shared.global [%0], [%1], 16;" :: "r"(dst), "l"(src));
}
__device__ __forceinline__ void cp_commit() {
    asm volatile("cp.async.commit_group;" ::: "memory");
}
__device__ __forceinline__ void cp_wait1() {
    asm volatile("cp.async.wait_group 1;" ::: "memory");
}
__device__ __forceinline__ void ldsm4(uint32_t& r0, uint32_t& r1, uint32_t& r2, uint32_t& r3, uint32_t addr) {
    asm volatile("ldmatrix.sync.aligned.m8n8.x4.shared.b16 {%0,%1,%2,%3}, [%4];"
                 : "=r"(r0), "=r"(r1), "=r"(r2), "=r"(r3) : "r"(addr));
}
__device__ __forceinline__ void mma16816(float* c, const uint32_t* a, const uint32_t* b) {
    asm volatile("mma.sync.aligned.m16n8k16.row.col.f32.f16.f16.f32 "
                 "{%0,%1,%2,%3}, {%4,%5,%6,%7}, {%8,%9}, {%0,%1,%2,%3};"
                 : "+f"(c[0]), "+f"(c[1]), "+f"(c[2]), "+f"(c[3])
                 : "r"(a[0]), "r"(a[1]), "r"(a[2]), "r"(a[3]), "r"(b[0]), "r"(b[1]));
}
__device__ __forceinline__ void split2h(float v, __half& h, __half& l) {
    h = __float2half_rn(v);
    l = __float2half_rn(v - __half2float(h));
}

// ---------------- kNN (K=3) ----------------
__global__ __launch_bounds__(256) void knn_kernel(
    const float* __restrict__ pos, const float* __restrict__ pos_skip,
    int* __restrict__ idx_out, float* __restrict__ w_out)
{
    __shared__ float sx[NC_PER], sy[NC_PER], sz[NC_PER], sn[NC_PER];
    int blk = blockIdx.x;
    int b = blk >> 4;
    const float* pc = pos + (size_t)b * NC_PER * 3;
    for (int i = threadIdx.x; i < NC_PER; i += 256) {
        float px = pc[i*3+0], py = pc[i*3+1], pz = pc[i*3+2];
        sx[i] = px; sy[i] = py; sz[i] = pz;
        sn[i] = px*px + py*py + pz*pz;
    }
    __syncthreads();
    int f = blk * 256 + threadIdx.x;
    float fx = pos_skip[f*3+0], fy = pos_skip[f*3+1], fz = pos_skip[f*3+2];
    float fn = fx*fx + fy*fy + fz*fz;
    float d0 = 3.4e38f, d1 = 3.4e38f, d2 = 3.4e38f;
    int   i0 = 0, i1 = 0, i2 = 0;
    for (int c = 0; c < NC_PER; ++c) {
        float dot = fx*sx[c] + fy*sy[c] + fz*sz[c];
        float dd  = fn + sn[c] - 2.0f*dot;
        if (dd < d2) {
            if (dd < d1) {
                if (dd < d0) { d2=d1; i2=i1; d1=d0; i1=i0; d0=dd; i0=c; }
                else         { d2=d1; i2=i1; d1=dd; i1=c; }
            } else           { d2=dd; i2=c; }
        }
    }
    float w0 = 1.0f / fmaxf(d0, 1e-16f);
    float w1 = 1.0f / fmaxf(d1, 1e-16f);
    float w2 = 1.0f / fmaxf(d2, 1e-16f);
    float inv = 1.0f / (w0 + w1 + w2);
    idx_out[f*3+0] = b * NC_PER + i0;
    idx_out[f*3+1] = b * NC_PER + i1;
    idx_out[f*3+2] = b * NC_PER + i2;
    w_out[f*3+0] = w0 * inv;
    w_out[f*3+1] = w1 * inv;
    w_out[f*3+2] = w2 * inv;
}

// ---------------- interpolate + concat -> fp16 hi/lo h0 ----------------
__global__ __launch_bounds__(128) void interp_kernel(
    const float* __restrict__ x, const float* __restrict__ x_skip)
{
    int f = blockIdx.x;
    int t = threadIdx.x;
    int ia = g_kidx[f*3+0], ib = g_kidx[f*3+1], ic = g_kidx[f*3+2];
    float w0 = g_kw[f*3+0], w1 = g_kw[f*3+1], w2 = g_kw[f*3+2];
    float4 a = ((const float4*)(x + (size_t)ia * C_IN))[t];
    float4 b = ((const float4*)(x + (size_t)ib * C_IN))[t];
    float4 c = ((const float4*)(x + (size_t)ic * C_IN))[t];
    float r[4];
    r[0] = w0*a.x + w1*b.x + w2*c.x;
    r[1] = w0*a.y + w1*b.y + w2*c.y;
    r[2] = w0*a.z + w1*b.z + w2*c.z;
    r[3] = w0*a.w + w1*b.w + w2*c.w;
    __half h[4], l[4];
    #pragma unroll
    for (int j = 0; j < 4; ++j) split2h(r[j], h[j], l[j]);
    size_t base = (size_t)f * D_IN + t * 4;
    *(uint2*)(g_h0hi + base) = *(uint2*)h;
    *(uint2*)(g_h0lo + base) = *(uint2*)l;
    if (t < C_SKIP / 4) {
        float4 s = ((const float4*)(x_skip + (size_t)f * C_SKIP))[t];
        float sv[4] = {s.x, s.y, s.z, s.w};
        #pragma unroll
        for (int j = 0; j < 4; ++j) split2h(sv[j], h[j], l[j]);
        size_t base2 = (size_t)f * D_IN + C_IN + t * 4;
        *(uint2*)(g_h0hi + base2) = *(uint2*)h;
        *(uint2*)(g_h0lo + base2) = *(uint2*)l;
    }
}

// ---------------- W transpose -> fp16: Wt[n][k] = W[k][n] ----------------
__global__ __launch_bounds__(256) void wsplit_kernel(
    const float* __restrict__ W, __half* __restrict__ hi, int Kd, int N)
{
    int id = blockIdx.x * 256 + threadIdx.x;
    if (id >= N * Kd) return;
    int n = id / Kd, k = id % Kd;
    hi[id] = __float2half_rn(W[(size_t)k * N + n]);
}

// ---------------- h1 -> BN1+ReLU -> fp16 hi/lo split ----------------
__global__ __launch_bounds__(256) void h1split_kernel()
{
    size_t i = (size_t)blockIdx.x * 256 + threadIdx.x;
    int cb = (int)(i & (C_OUT/4 - 1));
    float4 hv = ((const float4*)g_h1)[i];
    float4 av = ((const float4*)g_a1)[cb];
    float4 cv = ((const float4*)g_c1)[cb];
    float v[4];
    v[0] = fmaxf(fmaf(av.x, hv.x, cv.x), 0.0f);
    v[1] = fmaxf(fmaf(av.y, hv.y, cv.y), 0.0f);
    v[2] = fmaxf(fmaf(av.z, hv.z, cv.z), 0.0f);
    v[3] = fmaxf(fmaf(av.w, hv.w, cv.w), 0.0f);
    __half h[4], l[4];
    #pragma unroll
    for (int j = 0; j < 4; ++j) split2h(v[j], h[j], l[j]);
    *(uint2*)(g_h1hi + i * 4) = *(uint2*)h;
    *(uint2*)(g_h1lo + i * 4) = *(uint2*)l;
}

// ---------------- HMMA fp16 split-A GEMM: 128(M)x256(N) tile, 512 thr, 3-stage ----------------
// C[M,512] = A[M,Kd] @ Wt[512,Kd]^T       (bias dropped: BN shift-invariant)
// D = Ahi*W + Alo*W  (A fp16 split-2; W single fp16; fp32 accum)
#define BK 64
#define A_BYTES 16384                    // 128x64 fp16
#define B_BYTES 32768                    // 256x64 fp16
#define STAGE_BYTES (2*A_BYTES + B_BYTES)     // 65536
#define STAGES 3
#define GEMM_SMEM (STAGES * STAGE_BYTES)      // 196608

__device__ __forceinline__ uint32_t swoff(int row, int c) {
    return (uint32_t)(row * 128 + ((c ^ (row & 7)) << 4));
}

__global__ __launch_bounds__(512, 1) void gemm_kernel(
    const __half* __restrict__ Ahi, const __half* __restrict__ Alo,
    const __half* __restrict__ B,
    float* __restrict__ C, int Kd, int nchunk)
{
    extern __shared__ __align__(128) char smem[];
    uint32_t sbase = smem_u32(smem);
    int tid  = threadIdx.x;
    int wid  = tid >> 5, lane = tid & 31;
    int m0 = blockIdx.y * 128;
    int n0 = blockIdx.x * 256;

    const __half* asrc[2] = { Ahi + (size_t)m0 * Kd, Alo + (size_t)m0 * Kd };
    const __half* bsrc = B + (size_t)n0 * Kd;

    auto issue = [&](int sidx, int k0) {
        uint32_t sb = sbase + (uint32_t)sidx * STAGE_BYTES;
        #pragma unroll
        for (int reg = 0; reg < 2; ++reg) {          // A hi/lo: 128 rows x 8 chunks
            uint32_t rb = sb + (uint32_t)reg * A_BYTES;
            const __half* src = asrc[reg];
            #pragma unroll
            for (int it = 0; it < 2; ++it) {
                int chunk = it * 512 + tid;
                int row = chunk >> 3, c = chunk & 7;
                cp16(rb + swoff(row, c), src + (size_t)row * Kd + k0 + c * 8);
            }
        }
        {                                            // B: 256 rows x 8 chunks
            uint32_t rb = sb + 2 * A_BYTES;
            #pragma unroll
            for (int it = 0; it < 4; ++it) {
                int chunk = it * 512 + tid;
                int row = chunk >> 3, c = chunk & 7;
                cp16(rb + swoff(row, c), bsrc + (size_t)row * Kd + k0 + c * 8);
            }
        }
    };

    issue(0, 0);   cp_commit();
    issue(1, BK);  cp_commit();

    // warp tiling: 4 (M) x 4 (N) warps; warp tile 32(M) x 64(N)
    int wm = wid & 3, wn = wid >> 2;
    int mbase = wm * 32, nbase = wn * 64;
    int sub = lane >> 3, l7 = lane & 7;

    float acc[2][8][4];
    #pragma unroll
    for (int i = 0; i < 2; ++i)
        #pragma unroll
        for (int j = 0; j < 8; ++j)
            #pragma unroll
            for (int q = 0; q < 4; ++q) acc[i][j][q] = 0.0f;

    int arow_l = mbase + ((sub & 1) << 3) + l7;
    int acol_s = (sub >> 1);
    int brow_l = nbase + ((sub >> 1) << 3) + l7;
    int bcol_s = (sub & 1);

    for (int cc = 0; cc < nchunk; ++cc) {
        cp_wait1();
        __syncthreads();
        if (cc + 2 < nchunk) issue((cc + 2) % STAGES, (cc + 2) * BK);
        cp_commit();

        uint32_t bb = sbase + (uint32_t)(cc % STAGES) * STAGE_BYTES;
        #pragma unroll
        for (int ks = 0; ks < 4; ++ks) {
            int achunk = ks * 2 + acol_s;
            int bchunk = ks * 2 + bcol_s;
            uint32_t ah[2][4], bh[8][2];
            #pragma unroll
            for (int mi = 0; mi < 2; ++mi) {
                uint32_t ao = swoff(arow_l + mi * 16, achunk);
                ldsm4(ah[mi][0], ah[mi][1], ah[mi][2], ah[mi][3], bb + ao);
            }
            #pragma unroll
            for (int pi = 0; pi < 4; ++pi) {
                uint32_t bo = swoff(brow_l + pi * 16, bchunk);
                ldsm4(bh[pi*2][0], bh[pi*2][1], bh[pi*2+1][0], bh[pi*2+1][1],
                      bb + 2 * A_BYTES + bo);
            }
            // P1: Ahi * W
            #pragma unroll
            for (int mi = 0; mi < 2; ++mi)
                #pragma unroll
                for (int ni = 0; ni < 8; ++ni)
                    mma16816(acc[mi][ni], ah[mi], bh[ni]);
            // P2: Alo * W  (load al into ah's registers after P1)
            #pragma unroll
            for (int mi = 0; mi < 2; ++mi) {
                uint32_t ao = swoff(arow_l + mi * 16, achunk);
                ldsm4(ah[mi][0], ah[mi][1], ah[mi][2], ah[mi][3], bb + A_BYTES + ao);
            }
            #pragma unroll
            for (int mi = 0; mi < 2; ++mi)
                #pragma unroll
                for (int ni = 0; ni < 8; ++ni)
                    mma16816(acc[mi][ni], ah[mi], bh[ni]);
        }
    }

    // ---- epilogue: fp32 store ----
    int grow = m0 + mbase + (lane >> 2);
    int gcol0 = n0 + nbase + (lane & 3) * 2;
    #pragma unroll
    for (int ni = 0; ni < 8; ++ni) {
        int col = gcol0 + ni * 8;
        #pragma unroll
        for (int mi = 0; mi < 2; ++mi) {
            int r = grow + mi * 16;
            *(float2*)(C + (size_t)r * C_OUT + col)       = make_float2(acc[mi][ni][0], acc[mi][ni][1]);
            *(float2*)(C + (size_t)(r + 8) * C_OUT + col) = make_float2(acc[mi][ni][2], acc[mi][ni][3]);
        }
    }
}

// ---------------- BN stats (two-stage, deterministic) ----------------
__global__ __launch_bounds__(256) void stats_kernel(const float* __restrict__ H)
{
    int r0 = blockIdx.x * 256;
    int t = threadIdx.x;
    float s0 = 0, q0 = 0, s1 = 0, q1 = 0;
    for (int r = r0; r < r0 + 256; ++r) {
        float v0 = H[(size_t)r * C_OUT + t];
        float v1 = H[(size_t)r * C_OUT + t + 256];
        s0 += v0; q0 += v0*v0;
        s1 += v1; q1 += v1*v1;
    }
    g_psum[blockIdx.x * C_OUT + t]       = s0;
    g_psq [blockIdx.x * C_OUT + t]       = q0;
    g_psum[blockIdx.x * C_OUT + t + 256] = s1;
    g_psq [blockIdx.x * C_OUT + t + 256] = q1;
}

__global__ __launch_bounds__(128) void finalize_kernel(
    const float* __restrict__ g, const float* __restrict__ be,
    float* __restrict__ a, float* __restrict__ c)
{
    int ch = blockIdx.x * 128 + threadIdx.x;
    float s = 0, q = 0;
    for (int p = 0; p < PSTATS; ++p) {
        s += g_psum[p * C_OUT + ch];
        q += g_psq [p * C_OUT + ch];
    }
    float mu  = s * (1.0f / NF_TOT);
    float var = q * (1.0f / NF_TOT) - mu * mu;
    float av  = g[ch] * rsqrtf(var + BN_EPS);
    a[ch] = av;
    c[ch] = be[ch] - mu * av;
}

// ---------------- final BN2 + ReLU -> out ----------------
__global__ __launch_bounds__(256) void apply_out_kernel(
    const float* __restrict__ H, float* __restrict__ out)
{
    size_t i = (size_t)blockIdx.x * 256 + threadIdx.x;
    int cb = (int)(i & (C_OUT/4 - 1));
    float4 h  = ((const float4*)H)[i];
    float4 av = ((const float4*)g_a2)[cb];
    float4 cv = ((const float4*)g_c2)[cb];
    float4 r;
    r.x = fmaxf(fmaf(av.x, h.x, cv.x), 0.0f);
    r.y = fmaxf(fmaf(av.y, h.y, cv.y), 0.0f);
    r.z = fmaxf(fmaf(av.z, h.z, cv.z), 0.0f);
    r.w = fmaxf(fmaf(av.w, h.w, cv.w), 0.0f);
    ((float4*)out)[i] = r;
}

// ---------------- tuple extras ----------------
__global__ __launch_bounds__(256) void extras_kernel(
    const float* __restrict__ pos_skip, float* __restrict__ out, int mode)
{
    int i = blockIdx.x * 256 + threadIdx.x;
    const size_t baseH = (size_t)NF_TOT * C_OUT;
    if (i < NF_TOT * 3) out[baseH + i] = pos_skip[i];
    if (i < NF_TOT) {
        if (mode == 1)
            out[baseH + NF_TOT*3 + i] = (float)(i >> 12);
        else if (mode == 2)
            ((long long*)(out + baseH + NF_TOT*3))[i] = (long long)(i >> 12);
    }
}

// ---------------- host ----------------
extern "C" void kernel_launch(void* const* d_in, const int* in_sizes, int n_in,
                              void* d_out, int out_size)
{
    const float* x        = (const float*)d_in[0];
    const float* pos      = (const float*)d_in[1];
    const float* x_skip   = (const float*)d_in[3];
    const float* pos_skip = (const float*)d_in[4];
    const float* W1  = (const float*)d_in[6];
    const float* g1  = (const float*)d_in[8];
    const float* be1 = (const float*)d_in[9];
    const float* W2  = (const float*)d_in[10];
    const float* g2  = (const float*)d_in[12];
    const float* be2 = (const float*)d_in[13];
    float* out = (float*)d_out;

    float *p_h1, *p_h2, *p_a1, *p_c1, *p_a2, *p_c2;
    cudaGetSymbolAddress((void**)&p_h1, g_h1);
    cudaGetSymbolAddress((void**)&p_h2, g_h2);
    cudaGetSymbolAddress((void**)&p_a1, g_a1);
    cudaGetSymbolAddress((void**)&p_c1, g_c1);
    cudaGetSymbolAddress((void**)&p_a2, g_a2);
    cudaGetSymbolAddress((void**)&p_c2, g_c2);
    int *p_kidx; float *p_kw;
    cudaGetSymbolAddress((void**)&p_kidx, g_kidx);
    cudaGetSymbolAddress((void**)&p_kw,   g_kw);
    __half *p_h0hi, *p_h0lo, *p_h1hi, *p_h1lo, *p_w1t, *p_w2t;
    cudaGetSymbolAddress((void**)&p_h0hi, g_h0hi);
    cudaGetSymbolAddress((void**)&p_h0lo, g_h0lo);
    cudaGetSymbolAddress((void**)&p_h1hi, g_h1hi);
    cudaGetSymbolAddress((void**)&p_h1lo, g_h1lo);
    cudaGetSymbolAddress((void**)&p_w1t, g_w1t);
    cudaGetSymbolAddress((void**)&p_w2t, g_w2t);

    cudaFuncSetAttribute(gemm_kernel, cudaFuncAttributeMaxDynamicSharedMemorySize, GEMM_SMEM);

    // weight prep (transpose + fp16)
    wsplit_kernel<<<(C_OUT * D_IN + 255) / 256, 256>>>(W1, p_w1t, D_IN, C_OUT);
    wsplit_kernel<<<(C_OUT * C_OUT + 255) / 256, 256>>>(W2, p_w2t, C_OUT, C_OUT);
    // 1) kNN
    knn_kernel<<<NF_TOT / 256, 256>>>(pos, pos_skip, p_kidx, p_kw);
    // 2) interpolate + concat -> h0 hi/lo (fp16)
    interp_kernel<<<NF_TOT, 128>>>(x, x_skip);
    // 3) GEMM1 -> h1 fp32
    {
        dim3 grid(C_OUT / 256, NF_TOT / 128);
        gemm_kernel<<<grid, 512, GEMM_SMEM>>>(p_h0hi, p_h0lo, p_w1t,
                                              p_h1, D_IN, D_IN / BK);
    }
    // 4) BN1 stats + affine coefs
    stats_kernel<<<NF_TOT / 256, 256>>>(p_h1);
    finalize_kernel<<<C_OUT / 128, 128>>>(g1, be1, p_a1, p_c1);
    // 5) BN1+ReLU+split -> h1 hi/lo (fp16)
    h1split_kernel<<<(NF_TOT * (C_OUT / 4)) / 256, 256>>>();
    // 6) GEMM2 -> h2 fp32
    {
        dim3 grid(C_OUT / 256, NF_TOT / 128);
        gemm_kernel<<<grid, 512, GEMM_SMEM>>>(p_h1hi, p_h1lo, p_w2t,
                                              p_h2, C_OUT, C_OUT / BK);
    }
    // 7) BN2 stats + affine coefs
    stats_kernel<<<NF_TOT / 256, 256>>>(p_h2);
    finalize_kernel<<<C_OUT / 128, 128>>>(g2, be2, p_a2, p_c2);
    // 8) BN2 + ReLU -> out
    apply_out_kernel<<<(NF_TOT * (C_OUT / 4)) / 256, 256>>>(p_h2, out);
    // 9) tuple extras
    {
        long long baseH = (long long)NF_TOT * C_OUT;
        long long rem = (long long)out_size - baseH - (long long)NF_TOT * 3;
        int mode = 0;
        if (rem >= 2LL * NF_TOT)      mode = 2;
        else if (rem >= (long long)NF_TOT) mode = 1;
        if ((long long)out_size >= baseH + (long long)NF_TOT * 3)
            extras_kernel<<<(NF_TOT * 3 + 255) / 256, 256>>>(pos_skip, out, mode);
    }
}

// round 10
// speedup vs baseline: 1.9489x; 1.3539x over previous
#include <cuda_runtime.h>
#include <cuda_fp16.h>
#include <cstdint>

// ---------------- problem constants ----------------
#define BATCHES   16
#define NC_PER    1024
#define NF_PER    4096
#define NC_TOT    (BATCHES * NC_PER)   // 16384
#define NF_TOT    (BATCHES * NF_PER)   // 65536
#define C_IN      512
#define C_SKIP    256
#define D_IN      (C_IN + C_SKIP)      // 768
#define C_OUT     512
#define BN_EPS    1e-5f
#define PSTATS    256

// ---------------- device scratch ----------------
__device__ __align__(128) __half g_h0[(size_t)NF_TOT * D_IN];
__device__ __align__(128) float  g_h1[(size_t)NF_TOT * C_OUT];
__device__ __align__(128) float  g_h2[(size_t)NF_TOT * C_OUT];
__device__ __align__(128) __half g_h1h[(size_t)NF_TOT * C_OUT];
__device__ __align__(128) __half g_w1t[(size_t)C_OUT * D_IN];
__device__ __align__(128) __half g_w2t[(size_t)C_OUT * C_OUT];
__device__ int   g_kidx[(size_t)NF_TOT * 3];
__device__ float g_kw[(size_t)NF_TOT * 3];
__device__ float g_psum[PSTATS * C_OUT];
__device__ float g_psq[PSTATS * C_OUT];
__device__ float g_a1[C_OUT], g_c1[C_OUT], g_a2[C_OUT], g_c2[C_OUT];

// ---------------- helpers ----------------
__device__ __forceinline__ uint32_t smem_u32(const void* p) {
    uint32_t a;
    asm("{ .reg .u64 t; cvta.to.shared.u64 t, %1; cvt.u32.u64 %0, t; }" : "=r"(a) : "l"(p));
    return a;
}
__device__ __forceinline__ void cp16(uint32_t dst, const void* src) {
    asm volatile("cp.async.cg.shared.global [%0], [%1], 16;" :: "r"(dst), "l"(src));
}
__device__ __forceinline__ void cp_commit() {
    asm volatile("cp.async.commit_group;" ::: "memory");
}
__device__ __forceinline__ void cp_wait1() {
    asm volatile("cp.async.wait_group 1;" ::: "memory");
}
__device__ __forceinline__ void ldsm4(uint32_t& r0, uint32_t& r1, uint32_t& r2, uint32_t& r3, uint32_t addr) {
    asm volatile("ldmatrix.sync.aligned.m8n8.x4.shared.b16 {%0,%1,%2,%3}, [%4];"
                 : "=r"(r0), "=r"(r1), "=r"(r2), "=r"(r3) : "r"(addr));
}
__device__ __forceinline__ void mma16816(float* c, const uint32_t* a, const uint32_t* b) {
    asm volatile("mma.sync.aligned.m16n8k16.row.col.f32.f16.f16.f32 "
                 "{%0,%1,%2,%3}, {%4,%5,%6,%7}, {%8,%9}, {%0,%1,%2,%3};"
                 : "+f"(c[0]), "+f"(c[1]), "+f"(c[2]), "+f"(c[3])
                 : "r"(a[0]), "r"(a[1]), "r"(a[2]), "r"(a[3]), "r"(b[0]), "r"(b[1]));
}

// ---------------- kNN (K=3) ----------------
__global__ __launch_bounds__(256) void knn_kernel(
    const float* __restrict__ pos, const float* __restrict__ pos_skip,
    int* __restrict__ idx_out, float* __restrict__ w_out)
{
    __shared__ float sx[NC_PER], sy[NC_PER], sz[NC_PER], sn[NC_PER];
    int blk = blockIdx.x;
    int b = blk >> 4;
    const float* pc = pos + (size_t)b * NC_PER * 3;
    for (int i = threadIdx.x; i < NC_PER; i += 256) {
        float px = pc[i*3+0], py = pc[i*3+1], pz = pc[i*3+2];
        sx[i] = px; sy[i] = py; sz[i] = pz;
        sn[i] = px*px + py*py + pz*pz;
    }
    __syncthreads();
    int f = blk * 256 + threadIdx.x;
    float fx = pos_skip[f*3+0], fy = pos_skip[f*3+1], fz = pos_skip[f*3+2];
    float fn = fx*fx + fy*fy + fz*fz;
    float d0 = 3.4e38f, d1 = 3.4e38f, d2 = 3.4e38f;
    int   i0 = 0, i1 = 0, i2 = 0;
    for (int c = 0; c < NC_PER; ++c) {
        float dot = fx*sx[c] + fy*sy[c] + fz*sz[c];
        float dd  = fn + sn[c] - 2.0f*dot;
        if (dd < d2) {
            if (dd < d1) {
                if (dd < d0) { d2=d1; i2=i1; d1=d0; i1=i0; d0=dd; i0=c; }
                else         { d2=d1; i2=i1; d1=dd; i1=c; }
            } else           { d2=dd; i2=c; }
        }
    }
    float w0 = 1.0f / fmaxf(d0, 1e-16f);
    float w1 = 1.0f / fmaxf(d1, 1e-16f);
    float w2 = 1.0f / fmaxf(d2, 1e-16f);
    float inv = 1.0f / (w0 + w1 + w2);
    idx_out[f*3+0] = b * NC_PER + i0;
    idx_out[f*3+1] = b * NC_PER + i1;
    idx_out[f*3+2] = b * NC_PER + i2;
    w_out[f*3+0] = w0 * inv;
    w_out[f*3+1] = w1 * inv;
    w_out[f*3+2] = w2 * inv;
}

// ---------------- interpolate + concat -> fp16 h0 ----------------
__global__ __launch_bounds__(128) void interp_kernel(
    const float* __restrict__ x, const float* __restrict__ x_skip)
{
    int f = blockIdx.x;
    int t = threadIdx.x;
    int ia = g_kidx[f*3+0], ib = g_kidx[f*3+1], ic = g_kidx[f*3+2];
    float w0 = g_kw[f*3+0], w1 = g_kw[f*3+1], w2 = g_kw[f*3+2];
    float4 a = ((const float4*)(x + (size_t)ia * C_IN))[t];
    float4 b = ((const float4*)(x + (size_t)ib * C_IN))[t];
    float4 c = ((const float4*)(x + (size_t)ic * C_IN))[t];
    __half h[4];
    h[0] = __float2half_rn(w0*a.x + w1*b.x + w2*c.x);
    h[1] = __float2half_rn(w0*a.y + w1*b.y + w2*c.y);
    h[2] = __float2half_rn(w0*a.z + w1*b.z + w2*c.z);
    h[3] = __float2half_rn(w0*a.w + w1*b.w + w2*c.w);
    *(uint2*)(g_h0 + (size_t)f * D_IN + t * 4) = *(uint2*)h;
    if (t < C_SKIP / 4) {
        float4 s = ((const float4*)(x_skip + (size_t)f * C_SKIP))[t];
        h[0] = __float2half_rn(s.x);
        h[1] = __float2half_rn(s.y);
        h[2] = __float2half_rn(s.z);
        h[3] = __float2half_rn(s.w);
        *(uint2*)(g_h0 + (size_t)f * D_IN + C_IN + t * 4) = *(uint2*)h;
    }
}

// ---------------- W transpose -> fp16: Wt[n][k] = W[k][n] ----------------
__global__ __launch_bounds__(256) void wsplit_kernel(
    const float* __restrict__ W, __half* __restrict__ hi, int Kd, int N)
{
    int id = blockIdx.x * 256 + threadIdx.x;
    if (id >= N * Kd) return;
    int n = id / Kd, k = id % Kd;
    hi[id] = __float2half_rn(W[(size_t)k * N + n]);
}

// ---------------- h1 -> BN1+ReLU -> fp16 ----------------
__global__ __launch_bounds__(256) void h1split_kernel()
{
    size_t i = (size_t)blockIdx.x * 256 + threadIdx.x;
    int cb = (int)(i & (C_OUT/4 - 1));
    float4 hv = ((const float4*)g_h1)[i];
    float4 av = ((const float4*)g_a1)[cb];
    float4 cv = ((const float4*)g_c1)[cb];
    __half h[4];
    h[0] = __float2half_rn(fmaxf(fmaf(av.x, hv.x, cv.x), 0.0f));
    h[1] = __float2half_rn(fmaxf(fmaf(av.y, hv.y, cv.y), 0.0f));
    h[2] = __float2half_rn(fmaxf(fmaf(av.z, hv.z, cv.z), 0.0f));
    h[3] = __float2half_rn(fmaxf(fmaf(av.w, hv.w, cv.w), 0.0f));
    *(uint2*)(g_h1h + i * 4) = *(uint2*)h;
}

// ---------------- fp16 HGEMM: 128(M)x256(N) tile, 512 thr, 3-stage ----------------
// C[M,512] = A[M,Kd] @ Wt[512,Kd]^T       (bias dropped: BN shift-invariant)
#define BK 64
#define A_BYTES 16384                    // 128x64 fp16
#define B_BYTES 32768                    // 256x64 fp16
#define STAGE_BYTES (A_BYTES + B_BYTES)  // 49152
#define STAGES 3
#define GEMM_SMEM (STAGES * STAGE_BYTES) // 147456

__device__ __forceinline__ uint32_t swoff(int row, int c) {
    return (uint32_t)(row * 128 + ((c ^ (row & 7)) << 4));
}

__global__ __launch_bounds__(512, 1) void gemm_kernel(
    const __half* __restrict__ A, const __half* __restrict__ B,
    float* __restrict__ C, int Kd, int nchunk)
{
    extern __shared__ __align__(128) char smem[];
    uint32_t sbase = smem_u32(smem);
    int tid  = threadIdx.x;
    int wid  = tid >> 5, lane = tid & 31;
    int m0 = blockIdx.y * 128;
    int n0 = blockIdx.x * 256;

    const __half* asrc = A + (size_t)m0 * Kd;
    const __half* bsrc = B + (size_t)n0 * Kd;

    auto issue = [&](int sidx, int k0) {
        uint32_t sb = sbase + (uint32_t)sidx * STAGE_BYTES;
        #pragma unroll
        for (int it = 0; it < 2; ++it) {             // A: 128 rows x 8 chunks
            int chunk = it * 512 + tid;
            int row = chunk >> 3, c = chunk & 7;
            cp16(sb + swoff(row, c), asrc + (size_t)row * Kd + k0 + c * 8);
        }
        uint32_t rb = sb + A_BYTES;                  // B: 256 rows x 8 chunks
        #pragma unroll
        for (int it = 0; it < 4; ++it) {
            int chunk = it * 512 + tid;
            int row = chunk >> 3, c = chunk & 7;
            cp16(rb + swoff(row, c), bsrc + (size_t)row * Kd + k0 + c * 8);
        }
    };

    issue(0, 0);   cp_commit();
    issue(1, BK);  cp_commit();

    // warp tiling: 4 (M) x 4 (N) warps; warp tile 32(M) x 64(N)
    int wm = wid & 3, wn = wid >> 2;
    int mbase = wm * 32, nbase = wn * 64;
    int sub = lane >> 3, l7 = lane & 7;

    float acc[2][8][4];
    #pragma unroll
    for (int i = 0; i < 2; ++i)
        #pragma unroll
        for (int j = 0; j < 8; ++j)
            #pragma unroll
            for (int q = 0; q < 4; ++q) acc[i][j][q] = 0.0f;

    int arow_l = mbase + ((sub & 1) << 3) + l7;
    int acol_s = (sub >> 1);
    int brow_l = nbase + ((sub >> 1) << 3) + l7;
    int bcol_s = (sub & 1);

    for (int cc = 0; cc < nchunk; ++cc) {
        cp_wait1();
        __syncthreads();
        if (cc + 2 < nchunk) issue((cc + 2) % STAGES, (cc + 2) * BK);
        cp_commit();

        uint32_t bb = sbase + (uint32_t)(cc % STAGES) * STAGE_BYTES;
        #pragma unroll
        for (int ks = 0; ks < 4; ++ks) {
            int achunk = ks * 2 + acol_s;
            int bchunk = ks * 2 + bcol_s;
            uint32_t ah[2][4], bh[8][2];
            #pragma unroll
            for (int mi = 0; mi < 2; ++mi) {
                uint32_t ao = swoff(arow_l + mi * 16, achunk);
                ldsm4(ah[mi][0], ah[mi][1], ah[mi][2], ah[mi][3], bb + ao);
            }
            #pragma unroll
            for (int pi = 0; pi < 4; ++pi) {
                uint32_t bo = swoff(brow_l + pi * 16, bchunk);
                ldsm4(bh[pi*2][0], bh[pi*2][1], bh[pi*2+1][0], bh[pi*2+1][1],
                      bb + A_BYTES + bo);
            }
            #pragma unroll
            for (int mi = 0; mi < 2; ++mi)
                #pragma unroll
                for (int ni = 0; ni < 8; ++ni)
                    mma16816(acc[mi][ni], ah[mi], bh[ni]);
        }
    }

    // ---- epilogue: fp32 store ----
    int grow = m0 + mbase + (lane >> 2);
    int gcol0 = n0 + nbase + (lane & 3) * 2;
    #pragma unroll
    for (int ni = 0; ni < 8; ++ni) {
        int col = gcol0 + ni * 8;
        #pragma unroll
        for (int mi = 0; mi < 2; ++mi) {
            int r = grow + mi * 16;
            *(float2*)(C + (size_t)r * C_OUT + col)       = make_float2(acc[mi][ni][0], acc[mi][ni][1]);
            *(float2*)(C + (size_t)(r + 8) * C_OUT + col) = make_float2(acc[mi][ni][2], acc[mi][ni][3]);
        }
    }
}

// ---------------- BN stats (two-stage, deterministic) ----------------
__global__ __launch_bounds__(256) void stats_kernel(const float* __restrict__ H)
{
    int r0 = blockIdx.x * 256;
    int t = threadIdx.x;
    float s0 = 0, q0 = 0, s1 = 0, q1 = 0;
    for (int r = r0; r < r0 + 256; ++r) {
        float v0 = H[(size_t)r * C_OUT + t];
        float v1 = H[(size_t)r * C_OUT + t + 256];
        s0 += v0; q0 += v0*v0;
        s1 += v1; q1 += v1*v1;
    }
    g_psum[blockIdx.x * C_OUT + t]       = s0;
    g_psq [blockIdx.x * C_OUT + t]       = q0;
    g_psum[blockIdx.x * C_OUT + t + 256] = s1;
    g_psq [blockIdx.x * C_OUT + t + 256] = q1;
}

__global__ __launch_bounds__(128) void finalize_kernel(
    const float* __restrict__ g, const float* __restrict__ be,
    float* __restrict__ a, float* __restrict__ c)
{
    int ch = blockIdx.x * 128 + threadIdx.x;
    float s = 0, q = 0;
    for (int p = 0; p < PSTATS; ++p) {
        s += g_psum[p * C_OUT + ch];
        q += g_psq [p * C_OUT + ch];
    }
    float mu  = s * (1.0f / NF_TOT);
    float var = q * (1.0f / NF_TOT) - mu * mu;
    float av  = g[ch] * rsqrtf(var + BN_EPS);
    a[ch] = av;
    c[ch] = be[ch] - mu * av;
}

// ---------------- final BN2 + ReLU -> out ----------------
__global__ __launch_bounds__(256) void apply_out_kernel(
    const float* __restrict__ H, float* __restrict__ out)
{
    size_t i = (size_t)blockIdx.x * 256 + threadIdx.x;
    int cb = (int)(i & (C_OUT/4 - 1));
    float4 h  = ((const float4*)H)[i];
    float4 av = ((const float4*)g_a2)[cb];
    float4 cv = ((const float4*)g_c2)[cb];
    float4 r;
    r.x = fmaxf(fmaf(av.x, h.x, cv.x), 0.0f);
    r.y = fmaxf(fmaf(av.y, h.y, cv.y), 0.0f);
    r.z = fmaxf(fmaf(av.z, h.z, cv.z), 0.0f);
    r.w = fmaxf(fmaf(av.w, h.w, cv.w), 0.0f);
    ((float4*)out)[i] = r;
}

// ---------------- tuple extras ----------------
__global__ __launch_bounds__(256) void extras_kernel(
    const float* __restrict__ pos_skip, float* __restrict__ out, int mode)
{
    int i = blockIdx.x * 256 + threadIdx.x;
    const size_t baseH = (size_t)NF_TOT * C_OUT;
    if (i < NF_TOT * 3) out[baseH + i] = pos_skip[i];
    if (i < NF_TOT) {
        if (mode == 1)
            out[baseH + NF_TOT*3 + i] = (float)(i >> 12);
        else if (mode == 2)
            ((long long*)(out + baseH + NF_TOT*3))[i] = (long long)(i >> 12);
    }
}

// ---------------- host ----------------
extern "C" void kernel_launch(void* const* d_in, const int* in_sizes, int n_in,
                              void* d_out, int out_size)
{
    const float* x        = (const float*)d_in[0];
    const float* pos      = (const float*)d_in[1];
    const float* x_skip   = (const float*)d_in[3];
    const float* pos_skip = (const float*)d_in[4];
    const float* W1  = (const float*)d_in[6];
    const float* g1  = (const float*)d_in[8];
    const float* be1 = (const float*)d_in[9];
    const float* W2  = (const float*)d_in[10];
    const float* g2  = (const float*)d_in[12];
    const float* be2 = (const float*)d_in[13];
    float* out = (float*)d_out;

    float *p_h1, *p_h2, *p_a1, *p_c1, *p_a2, *p_c2;
    cudaGetSymbolAddress((void**)&p_h1, g_h1);
    cudaGetSymbolAddress((void**)&p_h2, g_h2);
    cudaGetSymbolAddress((void**)&p_a1, g_a1);
    cudaGetSymbolAddress((void**)&p_c1, g_c1);
    cudaGetSymbolAddress((void**)&p_a2, g_a2);
    cudaGetSymbolAddress((void**)&p_c2, g_c2);
    int *p_kidx; float *p_kw;
    cudaGetSymbolAddress((void**)&p_kidx, g_kidx);
    cudaGetSymbolAddress((void**)&p_kw,   g_kw);
    __half *p_h0, *p_h1h, *p_w1t, *p_w2t;
    cudaGetSymbolAddress((void**)&p_h0, g_h0);
    cudaGetSymbolAddress((void**)&p_h1h, g_h1h);
    cudaGetSymbolAddress((void**)&p_w1t, g_w1t);
    cudaGetSymbolAddress((void**)&p_w2t, g_w2t);

    cudaFuncSetAttribute(gemm_kernel, cudaFuncAttributeMaxDynamicSharedMemorySize, GEMM_SMEM);

    // weight prep (transpose + fp16)
    wsplit_kernel<<<(C_OUT * D_IN + 255) / 256, 256>>>(W1, p_w1t, D_IN, C_OUT);
    wsplit_kernel<<<(C_OUT * C_OUT + 255) / 256, 256>>>(W2, p_w2t, C_OUT, C_OUT);
    // 1) kNN
    knn_kernel<<<NF_TOT / 256, 256>>>(pos, pos_skip, p_kidx, p_kw);
    // 2) interpolate + concat -> h0 (fp16)
    interp_kernel<<<NF_TOT, 128>>>(x, x_skip);
    // 3) GEMM1 -> h1 fp32
    {
        dim3 grid(C_OUT / 256, NF_TOT / 128);
        gemm_kernel<<<grid, 512, GEMM_SMEM>>>(p_h0, p_w1t, p_h1, D_IN, D_IN / BK);
    }
    // 4) BN1 stats + affine coefs
    stats_kernel<<<NF_TOT / 256, 256>>>(p_h1);
    finalize_kernel<<<C_OUT / 128, 128>>>(g1, be1, p_a1, p_c1);
    // 5) BN1+ReLU -> h1 fp16
    h1split_kernel<<<(NF_TOT * (C_OUT / 4)) / 256, 256>>>();
    // 6) GEMM2 -> h2 fp32
    {
        dim3 grid(C_OUT / 256, NF_TOT / 128);
        gemm_kernel<<<grid, 512, GEMM_SMEM>>>(p_h1h, p_w2t, p_h2, C_OUT, C_OUT / BK);
    }
    // 7) BN2 stats + affine coefs
    stats_kernel<<<NF_TOT / 256, 256>>>(p_h2);
    finalize_kernel<<<C_OUT / 128, 128>>>(g2, be2, p_a2, p_c2);
    // 8) BN2 + ReLU -> out
    apply_out_kernel<<<(NF_TOT * (C_OUT / 4)) / 256, 256>>>(p_h2, out);
    // 9) tuple extras
    {
        long long baseH = (long long)NF_TOT * C_OUT;
        long long rem = (long long)out_size - baseH - (long long)NF_TOT * 3;
        int mode = 0;
        if (rem >= 2LL * NF_TOT)      mode = 2;
        else if (rem >= (long long)NF_TOT) mode = 1;
        if ((long long)out_size >= baseH + (long long)NF_TOT * 3)
            extras_kernel<<<(NF_TOT * 3 + 255) / 256, 256>>>(pos_skip, out, mode);
    }
}

// round 11
// speedup vs baseline: 2.0604x; 1.0572x over previous
#include <cuda_runtime.h>
#include <cuda_fp16.h>
#include <cstdint>

// ---------------- problem constants ----------------
#define BATCHES   16
#define NC_PER    1024
#define NF_PER    4096
#define NC_TOT    (BATCHES * NC_PER)   // 16384
#define NF_TOT    (BATCHES * NF_PER)   // 65536
#define C_IN      512
#define C_SKIP    256
#define D_IN      (C_IN + C_SKIP)      // 768
#define C_OUT     512
#define BN_EPS    1e-5f
#define PSTATS    256

// ---------------- device scratch ----------------
__device__ __align__(128) __half g_h0[(size_t)NF_TOT * D_IN];
__device__ __align__(128) __half g_h1r[(size_t)NF_TOT * C_OUT];  // raw GEMM1 out (fp16)
__device__ __align__(128) __half g_h1h[(size_t)NF_TOT * C_OUT];  // post-BN1 fp16 (GEMM2 A)
__device__ __align__(128) __half g_h2r[(size_t)NF_TOT * C_OUT];  // raw GEMM2 out (fp16)
__device__ __align__(128) __half g_w1t[(size_t)C_OUT * D_IN];
__device__ __align__(128) __half g_w2t[(size_t)C_OUT * C_OUT];
__device__ int   g_kidx[(size_t)NF_TOT * 3];
__device__ float g_kw[(size_t)NF_TOT * 3];
__device__ float g_psum[PSTATS * C_OUT];
__device__ float g_psq[PSTATS * C_OUT];
__device__ float g_a1[C_OUT], g_c1[C_OUT], g_a2[C_OUT], g_c2[C_OUT];

// ---------------- helpers ----------------
__device__ __forceinline__ uint32_t smem_u32(const void* p) {
    uint32_t a;
    asm("{ .reg .u64 t; cvta.to.shared.u64 t, %1; cvt.u32.u64 %0, t; }" : "=r"(a) : "l"(p));
    return a;
}
__device__ __forceinline__ void cp16(uint32_t dst, const void* src) {
    asm volatile("cp.async.cg.shared.global [%0], [%1], 16;" :: "r"(dst), "l"(src));
}
__device__ __forceinline__ void cp_commit() {
    asm volatile("cp.async.commit_group;" ::: "memory");
}
__device__ __forceinline__ void cp_wait1() {
    asm volatile("cp.async.wait_group 1;" ::: "memory");
}
__device__ __forceinline__ void ldsm4(uint32_t& r0, uint32_t& r1, uint32_t& r2, uint32_t& r3, uint32_t addr) {
    asm volatile("ldmatrix.sync.aligned.m8n8.x4.shared.b16 {%0,%1,%2,%3}, [%4];"
                 : "=r"(r0), "=r"(r1), "=r"(r2), "=r"(r3) : "r"(addr));
}
__device__ __forceinline__ void mma16816(float* c, const uint32_t* a, const uint32_t* b) {
    asm volatile("mma.sync.aligned.m16n8k16.row.col.f32.f16.f16.f32 "
                 "{%0,%1,%2,%3}, {%4,%5,%6,%7}, {%8,%9}, {%0,%1,%2,%3};"
                 : "+f"(c[0]), "+f"(c[1]), "+f"(c[2]), "+f"(c[3])
                 : "r"(a[0]), "r"(a[1]), "r"(a[2]), "r"(a[3]), "r"(b[0]), "r"(b[1]));
}

// ---------------- kNN (K=3) ----------------
__global__ __launch_bounds__(256) void knn_kernel(
    const float* __restrict__ pos, const float* __restrict__ pos_skip,
    int* __restrict__ idx_out, float* __restrict__ w_out)
{
    __shared__ float sx[NC_PER], sy[NC_PER], sz[NC_PER], sn[NC_PER];
    int blk = blockIdx.x;
    int b = blk >> 4;
    const float* pc = pos + (size_t)b * NC_PER * 3;
    for (int i = threadIdx.x; i < NC_PER; i += 256) {
        float px = pc[i*3+0], py = pc[i*3+1], pz = pc[i*3+2];
        sx[i] = px; sy[i] = py; sz[i] = pz;
        sn[i] = px*px + py*py + pz*pz;
    }
    __syncthreads();
    int f = blk * 256 + threadIdx.x;
    float fx = pos_skip[f*3+0], fy = pos_skip[f*3+1], fz = pos_skip[f*3+2];
    float fn = fx*fx + fy*fy + fz*fz;
    float d0 = 3.4e38f, d1 = 3.4e38f, d2 = 3.4e38f;
    int   i0 = 0, i1 = 0, i2 = 0;
    for (int c = 0; c < NC_PER; ++c) {
        float dot = fx*sx[c] + fy*sy[c] + fz*sz[c];
        float dd  = fn + sn[c] - 2.0f*dot;
        if (dd < d2) {
            if (dd < d1) {
                if (dd < d0) { d2=d1; i2=i1; d1=d0; i1=i0; d0=dd; i0=c; }
                else         { d2=d1; i2=i1; d1=dd; i1=c; }
            } else           { d2=dd; i2=c; }
        }
    }
    float w0 = 1.0f / fmaxf(d0, 1e-16f);
    float w1 = 1.0f / fmaxf(d1, 1e-16f);
    float w2 = 1.0f / fmaxf(d2, 1e-16f);
    float inv = 1.0f / (w0 + w1 + w2);
    idx_out[f*3+0] = b * NC_PER + i0;
    idx_out[f*3+1] = b * NC_PER + i1;
    idx_out[f*3+2] = b * NC_PER + i2;
    w_out[f*3+0] = w0 * inv;
    w_out[f*3+1] = w1 * inv;
    w_out[f*3+2] = w2 * inv;
}

// ---------------- interpolate + concat -> fp16 h0 ----------------
__global__ __launch_bounds__(128) void interp_kernel(
    const float* __restrict__ x, const float* __restrict__ x_skip)
{
    int f = blockIdx.x;
    int t = threadIdx.x;
    int ia = g_kidx[f*3+0], ib = g_kidx[f*3+1], ic = g_kidx[f*3+2];
    float w0 = g_kw[f*3+0], w1 = g_kw[f*3+1], w2 = g_kw[f*3+2];
    float4 a = ((const float4*)(x + (size_t)ia * C_IN))[t];
    float4 b = ((const float4*)(x + (size_t)ib * C_IN))[t];
    float4 c = ((const float4*)(x + (size_t)ic * C_IN))[t];
    __half h[4];
    h[0] = __float2half_rn(w0*a.x + w1*b.x + w2*c.x);
    h[1] = __float2half_rn(w0*a.y + w1*b.y + w2*c.y);
    h[2] = __float2half_rn(w0*a.z + w1*b.z + w2*c.z);
    h[3] = __float2half_rn(w0*a.w + w1*b.w + w2*c.w);
    *(uint2*)(g_h0 + (size_t)f * D_IN + t * 4) = *(uint2*)h;
    if (t < C_SKIP / 4) {
        float4 s = ((const float4*)(x_skip + (size_t)f * C_SKIP))[t];
        h[0] = __float2half_rn(s.x);
        h[1] = __float2half_rn(s.y);
        h[2] = __float2half_rn(s.z);
        h[3] = __float2half_rn(s.w);
        *(uint2*)(g_h0 + (size_t)f * D_IN + C_IN + t * 4) = *(uint2*)h;
    }
}

// ---------------- W transpose -> fp16: Wt[n][k] = W[k][n] ----------------
__global__ __launch_bounds__(256) void wsplit_kernel(
    const float* __restrict__ W, __half* __restrict__ hi, int Kd, int N)
{
    int id = blockIdx.x * 256 + threadIdx.x;
    if (id >= N * Kd) return;
    int n = id / Kd, k = id % Kd;
    hi[id] = __float2half_rn(W[(size_t)k * N + n]);
}

// ---------------- h1r (fp16) -> BN1+ReLU -> fp16 ----------------
__global__ __launch_bounds__(256) void h1split_kernel()
{
    size_t i = (size_t)blockIdx.x * 256 + threadIdx.x;   // one uint2 = 4 halves
    int cb = (int)(i & (C_OUT/4 - 1));
    uint2 w = ((const uint2*)g_h1r)[i];
    float4 av = ((const float4*)g_a1)[cb];
    float4 cv = ((const float4*)g_c1)[cb];
    float2 v0 = __half22float2(*(__half2*)&w.x);
    float2 v1 = __half22float2(*(__half2*)&w.y);
    __half h[4];
    h[0] = __float2half_rn(fmaxf(fmaf(av.x, v0.x, cv.x), 0.0f));
    h[1] = __float2half_rn(fmaxf(fmaf(av.y, v0.y, cv.y), 0.0f));
    h[2] = __float2half_rn(fmaxf(fmaf(av.z, v1.x, cv.z), 0.0f));
    h[3] = __float2half_rn(fmaxf(fmaf(av.w, v1.y, cv.w), 0.0f));
    ((uint2*)g_h1h)[i] = *(uint2*)h;
}

// ---------------- fp16 HGEMM: 128(M)x256(N) tile, 512 thr, 3-stage, fp16 out ----------------
// C[M,512] = A[M,Kd] @ Wt[512,Kd]^T       (bias dropped: BN shift-invariant)
#define BK 64
#define A_BYTES 16384                    // 128x64 fp16
#define B_BYTES 32768                    // 256x64 fp16
#define STAGE_BYTES (A_BYTES + B_BYTES)  // 49152
#define STAGES 3
#define GEMM_SMEM (STAGES * STAGE_BYTES) // 147456

__device__ __forceinline__ uint32_t swoff(int row, int c) {
    return (uint32_t)(row * 128 + ((c ^ (row & 7)) << 4));
}

__global__ __launch_bounds__(512, 1) void gemm_kernel(
    const __half* __restrict__ A, const __half* __restrict__ B,
    __half* __restrict__ C, int Kd, int nchunk)
{
    extern __shared__ __align__(128) char smem[];
    uint32_t sbase = smem_u32(smem);
    int tid  = threadIdx.x;
    int wid  = tid >> 5, lane = tid & 31;
    int m0 = blockIdx.y * 128;
    int n0 = blockIdx.x * 256;

    const __half* asrc = A + (size_t)m0 * Kd;
    const __half* bsrc = B + (size_t)n0 * Kd;

    auto issue = [&](int sidx, int k0) {
        uint32_t sb = sbase + (uint32_t)sidx * STAGE_BYTES;
        #pragma unroll
        for (int it = 0; it < 2; ++it) {             // A: 128 rows x 8 chunks
            int chunk = it * 512 + tid;
            int row = chunk >> 3, c = chunk & 7;
            cp16(sb + swoff(row, c), asrc + (size_t)row * Kd + k0 + c * 8);
        }
        uint32_t rb = sb + A_BYTES;                  // B: 256 rows x 8 chunks
        #pragma unroll
        for (int it = 0; it < 4; ++it) {
            int chunk = it * 512 + tid;
            int row = chunk >> 3, c = chunk & 7;
            cp16(rb + swoff(row, c), bsrc + (size_t)row * Kd + k0 + c * 8);
        }
    };

    issue(0, 0);   cp_commit();
    issue(1, BK);  cp_commit();

    // warp tiling: 4 (M) x 4 (N) warps; warp tile 32(M) x 64(N)
    int wm = wid & 3, wn = wid >> 2;
    int mbase = wm * 32, nbase = wn * 64;
    int sub = lane >> 3, l7 = lane & 7;

    float acc[2][8][4];
    #pragma unroll
    for (int i = 0; i < 2; ++i)
        #pragma unroll
        for (int j = 0; j < 8; ++j)
            #pragma unroll
            for (int q = 0; q < 4; ++q) acc[i][j][q] = 0.0f;

    int arow_l = mbase + ((sub & 1) << 3) + l7;
    int acol_s = (sub >> 1);
    int brow_l = nbase + ((sub >> 1) << 3) + l7;
    int bcol_s = (sub & 1);

    for (int cc = 0; cc < nchunk; ++cc) {
        cp_wait1();
        __syncthreads();
        if (cc + 2 < nchunk) issue((cc + 2) % STAGES, (cc + 2) * BK);
        cp_commit();

        uint32_t bb = sbase + (uint32_t)(cc % STAGES) * STAGE_BYTES;
        #pragma unroll
        for (int ks = 0; ks < 4; ++ks) {
            int achunk = ks * 2 + acol_s;
            int bchunk = ks * 2 + bcol_s;
            uint32_t ah[2][4], bh[8][2];
            #pragma unroll
            for (int mi = 0; mi < 2; ++mi) {
                uint32_t ao = swoff(arow_l + mi * 16, achunk);
                ldsm4(ah[mi][0], ah[mi][1], ah[mi][2], ah[mi][3], bb + ao);
            }
            #pragma unroll
            for (int pi = 0; pi < 4; ++pi) {
                uint32_t bo = swoff(brow_l + pi * 16, bchunk);
                ldsm4(bh[pi*2][0], bh[pi*2][1], bh[pi*2+1][0], bh[pi*2+1][1],
                      bb + A_BYTES + bo);
            }
            #pragma unroll
            for (int mi = 0; mi < 2; ++mi)
                #pragma unroll
                for (int ni = 0; ni < 8; ++ni)
                    mma16816(acc[mi][ni], ah[mi], bh[ni]);
        }
    }

    // ---- epilogue: fp16 (half2) store ----
    int grow = m0 + mbase + (lane >> 2);
    int gcol0 = n0 + nbase + (lane & 3) * 2;
    #pragma unroll
    for (int ni = 0; ni < 8; ++ni) {
        int col = gcol0 + ni * 8;
        #pragma unroll
        for (int mi = 0; mi < 2; ++mi) {
            int r = grow + mi * 16;
            *(__half2*)(C + (size_t)r * C_OUT + col) =
                __floats2half2_rn(acc[mi][ni][0], acc[mi][ni][1]);
            *(__half2*)(C + (size_t)(r + 8) * C_OUT + col) =
                __floats2half2_rn(acc[mi][ni][2], acc[mi][ni][3]);
        }
    }
}

// ---------------- BN stats from fp16 H (two-stage, deterministic) ----------------
// thread t covers channels 2t, 2t+1 (one half2 per row)
__global__ __launch_bounds__(256) void stats_kernel(const __half* __restrict__ H)
{
    int r0 = blockIdx.x * 256;
    int t = threadIdx.x;
    float s0 = 0, q0 = 0, s1 = 0, q1 = 0;
    const __half2* H2 = (const __half2*)H;
    for (int r = r0; r < r0 + 256; ++r) {
        float2 v = __half22float2(H2[(size_t)r * (C_OUT/2) + t]);
        s0 += v.x; q0 += v.x*v.x;
        s1 += v.y; q1 += v.y*v.y;
    }
    g_psum[blockIdx.x * C_OUT + 2*t]     = s0;
    g_psq [blockIdx.x * C_OUT + 2*t]     = q0;
    g_psum[blockIdx.x * C_OUT + 2*t + 1] = s1;
    g_psq [blockIdx.x * C_OUT + 2*t + 1] = q1;
}

__global__ __launch_bounds__(128) void finalize_kernel(
    const float* __restrict__ g, const float* __restrict__ be,
    float* __restrict__ a, float* __restrict__ c)
{
    int ch = blockIdx.x * 128 + threadIdx.x;
    float s = 0, q = 0;
    for (int p = 0; p < PSTATS; ++p) {
        s += g_psum[p * C_OUT + ch];
        q += g_psq [p * C_OUT + ch];
    }
    float mu  = s * (1.0f / NF_TOT);
    float var = q * (1.0f / NF_TOT) - mu * mu;
    float av  = g[ch] * rsqrtf(var + BN_EPS);
    a[ch] = av;
    c[ch] = be[ch] - mu * av;
}

// ---------------- final BN2 + ReLU from fp16 h2 -> fp32 out ----------------
__global__ __launch_bounds__(256) void apply_out_kernel(
    const __half* __restrict__ H, float* __restrict__ out)
{
    size_t i = (size_t)blockIdx.x * 256 + threadIdx.x;   // one uint2 = 4 halves
    int cb = (int)(i & (C_OUT/4 - 1));
    uint2 w = ((const uint2*)H)[i];
    float4 av = ((const float4*)g_a2)[cb];
    float4 cv = ((const float4*)g_c2)[cb];
    float2 v0 = __half22float2(*(__half2*)&w.x);
    float2 v1 = __half22float2(*(__half2*)&w.y);
    float4 r;
    r.x = fmaxf(fmaf(av.x, v0.x, cv.x), 0.0f);
    r.y = fmaxf(fmaf(av.y, v0.y, cv.y), 0.0f);
    r.z = fmaxf(fmaf(av.z, v1.x, cv.z), 0.0f);
    r.w = fmaxf(fmaf(av.w, v1.y, cv.w), 0.0f);
    ((float4*)out)[i] = r;
}

// ---------------- tuple extras ----------------
__global__ __launch_bounds__(256) void extras_kernel(
    const float* __restrict__ pos_skip, float* __restrict__ out, int mode)
{
    int i = blockIdx.x * 256 + threadIdx.x;
    const size_t baseH = (size_t)NF_TOT * C_OUT;
    if (i < NF_TOT * 3) out[baseH + i] = pos_skip[i];
    if (i < NF_TOT) {
        if (mode == 1)
            out[baseH + NF_TOT*3 + i] = (float)(i >> 12);
        else if (mode == 2)
            ((long long*)(out + baseH + NF_TOT*3))[i] = (long long)(i >> 12);
    }
}

// ---------------- host ----------------
extern "C" void kernel_launch(void* const* d_in, const int* in_sizes, int n_in,
                              void* d_out, int out_size)
{
    const float* x        = (const float*)d_in[0];
    const float* pos      = (const float*)d_in[1];
    const float* x_skip   = (const float*)d_in[3];
    const float* pos_skip = (const float*)d_in[4];
    const float* W1  = (const float*)d_in[6];
    const float* g1  = (const float*)d_in[8];
    const float* be1 = (const float*)d_in[9];
    const float* W2  = (const float*)d_in[10];
    const float* g2  = (const float*)d_in[12];
    const float* be2 = (const float*)d_in[13];
    float* out = (float*)d_out;

    float *p_a1, *p_c1, *p_a2, *p_c2;
    cudaGetSymbolAddress((void**)&p_a1, g_a1);
    cudaGetSymbolAddress((void**)&p_c1, g_c1);
    cudaGetSymbolAddress((void**)&p_a2, g_a2);
    cudaGetSymbolAddress((void**)&p_c2, g_c2);
    int *p_kidx; float *p_kw;
    cudaGetSymbolAddress((void**)&p_kidx, g_kidx);
    cudaGetSymbolAddress((void**)&p_kw,   g_kw);
    __half *p_h0, *p_h1r, *p_h1h, *p_h2r, *p_w1t, *p_w2t;
    cudaGetSymbolAddress((void**)&p_h0, g_h0);
    cudaGetSymbolAddress((void**)&p_h1r, g_h1r);
    cudaGetSymbolAddress((void**)&p_h1h, g_h1h);
    cudaGetSymbolAddress((void**)&p_h2r, g_h2r);
    cudaGetSymbolAddress((void**)&p_w1t, g_w1t);
    cudaGetSymbolAddress((void**)&p_w2t, g_w2t);

    cudaFuncSetAttribute(gemm_kernel, cudaFuncAttributeMaxDynamicSharedMemorySize, GEMM_SMEM);

    // weight prep (transpose + fp16)
    wsplit_kernel<<<(C_OUT * D_IN + 255) / 256, 256>>>(W1, p_w1t, D_IN, C_OUT);
    wsplit_kernel<<<(C_OUT * C_OUT + 255) / 256, 256>>>(W2, p_w2t, C_OUT, C_OUT);
    // 1) kNN
    knn_kernel<<<NF_TOT / 256, 256>>>(pos, pos_skip, p_kidx, p_kw);
    // 2) interpolate + concat -> h0 (fp16)
    interp_kernel<<<NF_TOT, 128>>>(x, x_skip);
    // 3) GEMM1 -> h1 raw fp16
    {
        dim3 grid(C_OUT / 256, NF_TOT / 128);
        gemm_kernel<<<grid, 512, GEMM_SMEM>>>(p_h0, p_w1t, p_h1r, D_IN, D_IN / BK);
    }
    // 4) BN1 stats (fp16) + affine coefs
    stats_kernel<<<NF_TOT / 256, 256>>>(p_h1r);
    finalize_kernel<<<C_OUT / 128, 128>>>(g1, be1, p_a1, p_c1);
    // 5) BN1+ReLU -> h1 fp16
    h1split_kernel<<<(NF_TOT * (C_OUT / 4)) / 256, 256>>>();
    // 6) GEMM2 -> h2 raw fp16
    {
        dim3 grid(C_OUT / 256, NF_TOT / 128);
        gemm_kernel<<<grid, 512, GEMM_SMEM>>>(p_h1h, p_w2t, p_h2r, C_OUT, C_OUT / BK);
    }
    // 7) BN2 stats (fp16) + affine coefs
    stats_kernel<<<NF_TOT / 256, 256>>>(p_h2r);
    finalize_kernel<<<C_OUT / 128, 128>>>(g2, be2, p_a2, p_c2);
    // 8) BN2 + ReLU -> out
    apply_out_kernel<<<(NF_TOT * (C_OUT / 4)) / 256, 256>>>(p_h2r, out);
    // 9) tuple extras
    {
        long long baseH = (long long)NF_TOT * C_OUT;
        long long rem = (long long)out_size - baseH - (long long)NF_TOT * 3;
        int mode = 0;
        if (rem >= 2LL * NF_TOT)      mode = 2;
        else if (rem >= (long long)NF_TOT) mode = 1;
        if ((long long)out_size >= baseH + (long long)NF_TOT * 3)
            extras_kernel<<<(NF_TOT * 3 + 255) / 256, 256>>>(pos_skip, out, mode);
    }
}